// round 11
// baseline (speedup 1.0000x reference)
#include <cuda_runtime.h>
#include <cuda_bf16.h>
#include <math.h>

#define B_SZ 4
#define T_SZ 2048
#define DM   1024
#define NH   16
#define DH   64
#define HALF 32   // DH/2

typedef unsigned int u32;

// ---------------- scratch (device globals; no runtime allocation) ----------------
__device__ float g_q[B_SZ*NH*T_SZ*DH];
__device__ float g_k[B_SZ*NH*T_SZ*DH];
__device__ float g_v[B_SZ*NH*T_SZ*DH];
__device__ float g_attn[B_SZ*T_SZ*DM];
__device__ float g_cos[T_SZ*HALF];
__device__ float g_sin[T_SZ*HALF];
__device__ float g_pm[64*4*32];
__device__ float g_pl[64*4*32];
__device__ float g_pacc[64*4*32*64];
// pre-converted bf16 hi/lo operands
__device__ __nv_bfloat16 g_xh[B_SZ*T_SZ*DM];
__device__ __nv_bfloat16 g_xl[B_SZ*T_SZ*DM];
__device__ __nv_bfloat16 g_wqh[DM*3*DM];
__device__ __nv_bfloat16 g_wql[DM*3*DM];
__device__ __nv_bfloat16 g_woh[DM*DM];
__device__ __nv_bfloat16 g_wol[DM*DM];
__device__ __nv_bfloat16 g_ah[B_SZ*T_SZ*DM];
__device__ __nv_bfloat16 g_al[B_SZ*T_SZ*DM];

// ---------------- GEMM tiling constants ----------------
#define KS        32          // k-step (bf16 elems)
#define NSTG      3
#define AH_OFF    0           // A hi: 128 rows x 40 bf16 (80B padded) = 10240B
#define AL_OFF    10240
#define BH_OFF    20480       // B hi: 32 rows x 136 bf16 (272B padded) = 8704B
#define BL_OFF    29184
#define STG_BYTES 37888
#define GEMM_SMEM (NSTG * STG_BYTES)   // 113664

// ---------------- tensor-core / async helpers ----------------
__device__ __forceinline__ void ldsm4(u32& r0, u32& r1, u32& r2, u32& r3, u32 a) {
    asm volatile("ldmatrix.sync.aligned.m8n8.x4.shared.b16 {%0,%1,%2,%3}, [%4];"
                 : "=r"(r0), "=r"(r1), "=r"(r2), "=r"(r3) : "r"(a));
}
__device__ __forceinline__ void ldsm4t(u32& r0, u32& r1, u32& r2, u32& r3, u32 a) {
    asm volatile("ldmatrix.sync.aligned.m8n8.x4.trans.shared.b16 {%0,%1,%2,%3}, [%4];"
                 : "=r"(r0), "=r"(r1), "=r"(r2), "=r"(r3) : "r"(a));
}
__device__ __forceinline__ void mma_bf16(float* d, const u32* a, const u32* b) {
    asm volatile("mma.sync.aligned.m16n8k16.row.col.f32.bf16.bf16.f32 "
                 "{%0,%1,%2,%3}, {%4,%5,%6,%7}, {%8,%9}, {%0,%1,%2,%3};"
                 : "+f"(d[0]), "+f"(d[1]), "+f"(d[2]), "+f"(d[3])
                 : "r"(a[0]), "r"(a[1]), "r"(a[2]), "r"(a[3]), "r"(b[0]), "r"(b[1]));
}
__device__ __forceinline__ void cpa16(u32 dst, const void* src) {
    asm volatile("cp.async.cg.shared.global [%0], [%1], 16;" :: "r"(dst), "l"(src) : "memory");
}
__device__ __forceinline__ void cpa_commit() {
    asm volatile("cp.async.commit_group;" ::: "memory");
}
template<int N> __device__ __forceinline__ void cpa_wait() {
    asm volatile("cp.async.wait_group %0;" :: "n"(N) : "memory");
}

// ---------------- cvt kernel ----------------
__global__ void cvt_split_kernel(const float* __restrict__ src,
                                 __nv_bfloat16* __restrict__ hi,
                                 __nv_bfloat16* __restrict__ lo, int n4) {
    int i = blockIdx.x * blockDim.x + threadIdx.x;
    if (i >= n4) return;
    float4 v = ((const float4*)src)[i];
    float vv[4] = {v.x, v.y, v.z, v.w};
    u32 hw[2];
    u32 lw[2];
#pragma unroll
    for (int p = 0; p < 2; p++) {
        __nv_bfloat16 h0 = __float2bfloat16(vv[2*p]);
        __nv_bfloat16 h1 = __float2bfloat16(vv[2*p+1]);
        __nv_bfloat16 l0 = __float2bfloat16(vv[2*p]   - __bfloat162float(h0));
        __nv_bfloat16 l1 = __float2bfloat16(vv[2*p+1] - __bfloat162float(h1));
        __nv_bfloat162 hp = __halves2bfloat162(h0, h1);
        __nv_bfloat162 lp = __halves2bfloat162(l0, l1);
        hw[p] = *(u32*)&hp;
        lw[p] = *(u32*)&lp;
    }
    ((uint2*)hi)[i] = make_uint2(hw[0], hw[1]);
    ((uint2*)lo)[i] = make_uint2(lw[0], lw[1]);
}

// ---------------- kernel 0: RoPE tables ----------------
__global__ void rope_table_kernel() {
    int idx = blockIdx.x * blockDim.x + threadIdx.x;
    if (idx >= T_SZ * HALF) return;
    int t = idx / HALF;
    int j = idx % HALF;
    double inv = pow(10000.0, -(double)j / (double)HALF);
    double ang = (double)t * inv;
    g_cos[idx] = (float)cos(ang);
    g_sin[idx] = (float)sin(ang);
}

// ---------------- 128x128 bf16-split GEMM, 512 threads, cp.async 3-stage --------
// 16 warps in a 4x4 grid; warp tile 32x32 (mi 2 x ni 4 m16n8 frags).
template<int LDB>
__device__ __forceinline__ void tc_gemm_bf16(
    const __nv_bfloat16* __restrict__ Ahg, const __nv_bfloat16* __restrict__ Alg,
    const __nv_bfloat16* __restrict__ Bhg, const __nv_bfloat16* __restrict__ Blg,
    float (&acc)[2][4][4])
{
    extern __shared__ char sm[];
    const u32 smb = (u32)__cvta_generic_to_shared(sm);
    const int tid  = threadIdx.x;
    const int lane = tid & 31;
    const int warp = tid >> 5;            // 0..15
    const int wm = warp >> 2;             // 0..3
    const int wn = warp & 3;              // 0..3
    const int arow = (lane & 7) + ((lane >> 3) & 1) * 8;
    const int akk  = ((lane >> 4) & 1) * 8;

    const int ar = tid >> 2;              // A row 0..127
    const int ac = (tid & 3) * 8;         // A elem chunk within k-step
    const int br = tid >> 4;              // B k-row 0..31
    const int bc = (tid & 15) * 8;        // B col chunk

#pragma unroll
    for (int mi = 0; mi < 2; mi++)
#pragma unroll
        for (int ni = 0; ni < 4; ni++)
#pragma unroll
            for (int r = 0; r < 4; r++)
                acc[mi][ni][r] = 0.f;

    const u32 a_soff = (u32)(ar * 80 + ac * 2);
    const u32 b_soff = (u32)(br * 272 + bc * 2);

#define ISSUE_STAGE(kt, st) do {                                                   \
        const __nv_bfloat16* ah = Ahg + (size_t)ar * DM + (kt) * KS + ac;          \
        const __nv_bfloat16* al = Alg + (size_t)ar * DM + (kt) * KS + ac;          \
        const __nv_bfloat16* bh = Bhg + (size_t)((kt) * KS + br) * LDB + bc;       \
        const __nv_bfloat16* bl = Blg + (size_t)((kt) * KS + br) * LDB + bc;       \
        const u32 sb = smb + (u32)(st) * STG_BYTES;                                \
        cpa16(sb + AH_OFF + a_soff, ah);                                           \
        cpa16(sb + AL_OFF + a_soff, al);                                           \
        cpa16(sb + BH_OFF + b_soff, bh);                                           \
        cpa16(sb + BL_OFF + b_soff, bl);                                           \
        cpa_commit();                                                              \
    } while (0)

    ISSUE_STAGE(0, 0);
    ISSUE_STAGE(1, 1);

    const int KT = DM / KS;               // 32
    for (int kt = 0; kt < KT; kt++) {
        if (kt == KT - 1) cpa_wait<0>(); else cpa_wait<1>();
        __syncthreads();
        if (kt + 2 < KT) ISSUE_STAGE(kt + 2, (kt + 2) % NSTG);

        const u32 sb = smb + (u32)(kt % NSTG) * STG_BYTES;
#pragma unroll
        for (int kh = 0; kh < 2; kh++) {
            u32 AH[2][4];
            u32 AL[2][4];
            u32 BH[4][2];
            u32 BL[4][2];
#pragma unroll
            for (int mi = 0; mi < 2; mi++) {
                const u32 adr = sb + (u32)((wm*32 + mi*16 + arow) * 80 + (kh*16 + akk) * 2);
                ldsm4(AH[mi][0], AH[mi][1], AH[mi][2], AH[mi][3], adr + AH_OFF);
                ldsm4(AL[mi][0], AL[mi][1], AL[mi][2], AL[mi][3], adr + AL_OFF);
            }
#pragma unroll
            for (int nj = 0; nj < 2; nj++) {
                const u32 bdr = sb + (u32)((kh*16 + arow) * 272 + (wn*32 + nj*16 + akk) * 2);
                u32 t0, t1, t2, t3;
                ldsm4t(t0, t1, t2, t3, bdr + BH_OFF);
                BH[nj*2][0] = t0;
                BH[nj*2][1] = t1;
                BH[nj*2+1][0] = t2;
                BH[nj*2+1][1] = t3;
                ldsm4t(t0, t1, t2, t3, bdr + BL_OFF);
                BL[nj*2][0] = t0;
                BL[nj*2][1] = t1;
                BL[nj*2+1][0] = t2;
                BL[nj*2+1][1] = t3;
            }
#pragma unroll
            for (int mi = 0; mi < 2; mi++) {
#pragma unroll
                for (int ni = 0; ni < 4; ni++) {
                    mma_bf16(acc[mi][ni], AH[mi], BH[ni]);
                    mma_bf16(acc[mi][ni], AH[mi], BL[ni]);
                    mma_bf16(acc[mi][ni], AL[mi], BH[ni]);
                }
            }
        }
    }
#undef ISSUE_STAGE
}

// ---------------- kernel 1: QKV GEMM + RoPE epilogue ----------------
__global__ __launch_bounds__(512) void qkv_tc_kernel() {
    const int row0 = blockIdx.y * 128;
    const int col0 = blockIdx.x * 128;
    float acc[2][4][4];
    tc_gemm_bf16<3072>(g_xh + (size_t)row0 * DM, g_xl + (size_t)row0 * DM,
                       g_wqh + col0, g_wql + col0, acc);

    const int lane = threadIdx.x & 31;
    const int warp = threadIdx.x >> 5;
    const int wm = warp >> 2;
    const int wn = warp & 3;
    const int r0c = lane >> 2;
    const int cp  = (lane & 3) * 2;
    const int which = col0 >> 10;                      // 0=q 1=k 2=v
    float* dst = (which == 0) ? g_q : ((which == 1) ? g_k : g_v);
    const bool dorope = (which < 2);

#pragma unroll
    for (int mi = 0; mi < 2; mi++) {
#pragma unroll
        for (int half = 0; half < 2; half++) {
            const int gm = row0 + wm*32 + mi*16 + r0c + half*8;
            const int bb = gm >> 11;
            const int t  = gm & (T_SZ - 1);
#pragma unroll
            for (int ni = 0; ni < 4; ni++) {
                const int gn  = col0 + wn*32 + ni*8 + cp;
                const int rem = gn & 1023;
                const int h = rem >> 6;
                const int d = rem & 63;
                float v0 = acc[mi][ni][half*2 + 0];
                float v1 = acc[mi][ni][half*2 + 1];
                if (dorope) {
                    const int j = d >> 1;
                    const float c = g_cos[t*HALF + j];
                    const float s = g_sin[t*HALF + j];
                    const float re = v0*c - v1*s;
                    const float ro = v0*s + v1*c;
                    v0 = re;
                    v1 = ro;
                }
                *(float2*)&dst[((size_t)(bb*NH + h) * T_SZ + t) * DH + d] = make_float2(v0, v1);
            }
        }
    }
}

// ---------------- kernel 3: out projection + bias ----------------
__global__ __launch_bounds__(512) void out_tc_kernel(const float* __restrict__ bias,
                                                     float* __restrict__ out) {
    const int row0 = blockIdx.y * 128;
    const int col0 = blockIdx.x * 128;
    float acc[2][4][4];
    tc_gemm_bf16<1024>(g_ah + (size_t)row0 * DM, g_al + (size_t)row0 * DM,
                       g_woh + col0, g_wol + col0, acc);

    const int lane = threadIdx.x & 31;
    const int warp = threadIdx.x >> 5;
    const int wm = warp >> 2;
    const int wn = warp & 3;
    const int r0c = lane >> 2;
    const int cp  = (lane & 3) * 2;

#pragma unroll
    for (int mi = 0; mi < 2; mi++) {
#pragma unroll
        for (int half = 0; half < 2; half++) {
            const int gm = row0 + wm*32 + mi*16 + r0c + half*8;
#pragma unroll
            for (int ni = 0; ni < 4; ni++) {
                const int gn = col0 + wn*32 + ni*8 + cp;
                const float b0 = bias[gn];
                const float b1 = bias[gn + 1];
                *(float2*)&out[(size_t)gm * DM + gn] =
                    make_float2(acc[mi][ni][half*2 + 0] + b0,
                                acc[mi][ni][half*2 + 1] + b1);
            }
        }
    }
}

// ---------------- shared attention tile body (pointer form) ----------------
__device__ __forceinline__ void attn_tile_body(
    float (*Qs)[64], float (*KP)[64], float (*Vs)[64],
    int tx, int ty, int qt, int kt, int jmax, bool global_tile,
    float (&m)[4], float (&l)[4], float (&acc)[4][4])
{
    float s[4][4];
#pragma unroll
    for (int i = 0; i < 4; i++)
#pragma unroll
        for (int j = 0; j < 4; j++) s[i][j] = 0.f;
#pragma unroll 16
    for (int d = 0; d < 64; d++) {
        float4 a = *(float4*)&Qs[d][ty*4];
        float4 b = *(float4*)&KP[d][tx*4];
        float ar[4] = {a.x, a.y, a.z, a.w};
        float br[4] = {b.x, b.y, b.z, b.w};
#pragma unroll
        for (int i = 0; i < 4; i++)
#pragma unroll
            for (int j = 0; j < 4; j++)
                s[i][j] = fmaf(ar[i], br[j], s[i][j]);
    }

    if (global_tile) {
#pragma unroll
        for (int i = 0; i < 4; i++)
#pragma unroll
            for (int j = 0; j < 4; j++) {
                const bool ok = (tx*4 + j) <= jmax;
                s[i][j] = ok ? s[i][j] * 0.125f : -1.0e9f;
            }
    } else {
        const int qb = qt * 64 + ty * 4;
        const int kb = kt * 64 + tx * 4;
#pragma unroll
        for (int i = 0; i < 4; i++) {
            const int q = qb + i;
            const bool qg = ((q & 63) == 0);
#pragma unroll
            for (int j = 0; j < 4; j++) {
                const int k = kb + j;
                const bool ok = (k <= q) && ((q - k) <= 127 || ((k & 63) == 0) || qg);
                s[i][j] = ok ? s[i][j] * 0.125f : -1.0e9f;
            }
        }
    }

    float rm[4];
#pragma unroll
    for (int i = 0; i < 4; i++)
        rm[i] = fmaxf(fmaxf(s[i][0], s[i][1]), fmaxf(s[i][2], s[i][3]));
#pragma unroll
    for (int off = 8; off > 0; off >>= 1)
#pragma unroll
        for (int i = 0; i < 4; i++)
            rm[i] = fmaxf(rm[i], __shfl_xor_sync(0xffffffffu, rm[i], off));

    float sc[4];
#pragma unroll
    for (int i = 0; i < 4; i++) {
        const float mn = fmaxf(m[i], rm[i]);
        sc[i] = __expf(m[i] - mn);
        m[i] = mn;
    }
    float rs[4];
#pragma unroll
    for (int i = 0; i < 4; i++) {
        float r = 0.f;
#pragma unroll
        for (int j = 0; j < 4; j++) {
            const float p = __expf(s[i][j] - m[i]);
            s[i][j] = p;
            r += p;
        }
        rs[i] = r;
    }
#pragma unroll
    for (int off = 8; off > 0; off >>= 1)
#pragma unroll
        for (int i = 0; i < 4; i++)
            rs[i] += __shfl_xor_sync(0xffffffffu, rs[i], off);
#pragma unroll
    for (int i = 0; i < 4; i++) {
        l[i] = l[i] * sc[i] + rs[i];
#pragma unroll
        for (int j = 0; j < 4; j++) acc[i][j] *= sc[i];
    }

    __syncthreads();
#pragma unroll
    for (int i = 0; i < 4; i++)
        *(float4*)&KP[ty*4 + i][tx*4] = make_float4(s[i][0], s[i][1], s[i][2], s[i][3]);
    __syncthreads();

#pragma unroll 8
    for (int kk = 0; kk < 64; kk += 4) {
        float4 a0 = *(float4*)&KP[ty*4 + 0][kk];
        float4 a1 = *(float4*)&KP[ty*4 + 1][kk];
        float4 a2 = *(float4*)&KP[ty*4 + 2][kk];
        float4 a3 = *(float4*)&KP[ty*4 + 3][kk];
        float ar[4][4] = {{a0.x,a0.y,a0.z,a0.w},{a1.x,a1.y,a1.z,a1.w},
                          {a2.x,a2.y,a2.z,a2.w},{a3.x,a3.y,a3.z,a3.w}};
#pragma unroll
        for (int u = 0; u < 4; u++) {
            float4 b = *(float4*)&Vs[kk + u][tx*4];
            float br[4] = {b.x, b.y, b.z, b.w};
#pragma unroll
            for (int i = 0; i < 4; i++)
#pragma unroll
                for (int j = 0; j < 4; j++)
                    acc[i][j] = fmaf(ar[i][u], br[j], acc[i][j]);
        }
    }
}

// ---------------- fused attention: main sparse flash + global-query partials ----
// Blocks [0, 2048): sparse flash (qt = bid & 31, bh = bid >> 5), 48KB dyn smem.
// Blocks [2048, 2304): global-query split-K partials (bh = id >> 2, kc = id & 3).
__global__ __launch_bounds__(256) void attn_fused_kernel() {
    extern __shared__ float smf[];
    const int bid = blockIdx.x;
    const int tid = threadIdx.x;
    const int tx = tid & 15, ty = tid >> 4;

    if (bid < 2048) {
        float (*Qs)[64] = (float(*)[64])smf;
        float (*KP)[64] = (float(*)[64])(smf + 64*64);
        float (*Vs)[64] = (float(*)[64])(smf + 2*64*64);
        const int qt = bid & 31;
        const int bh = bid >> 5;
        const float* qptr = g_q + (bh * T_SZ + qt * 64) * DH;
        const float* kptr = g_k + bh * T_SZ * DH;
        const float* vptr = g_v + bh * T_SZ * DH;

        {
            const int row = tid >> 2;
            const int cc  = tid & 3;
#pragma unroll
            for (int u = 0; u < 4; u++) {
                const int d0 = (cc + 4 * u) * 4;
                float4 qv = *(const float4*)&qptr[row * DH + d0];
                Qs[d0+0][row] = qv.x; Qs[d0+1][row] = qv.y;
                Qs[d0+2][row] = qv.z; Qs[d0+3][row] = qv.w;
            }
        }

        float m[4], l[4], acc[4][4];
#pragma unroll
        for (int i = 0; i < 4; i++) {
            m[i] = -1e30f; l[i] = 0.f;
#pragma unroll
            for (int j = 0; j < 4; j++) acc[i][j] = 0.f;
        }

        if (qt >= 3) {
            const int jmax = qt - 3;
            const int row = tid >> 2;
            const int cc  = tid & 3;
            const bool valid = (row <= jmax);
#pragma unroll
            for (int u = 0; u < 4; u++) {
                const int d0 = (cc + 4 * u) * 4;
                if (valid) {
                    float4 kv = *(const float4*)&kptr[(row << 6) * DH + d0];
                    KP[d0+0][row] = kv.x; KP[d0+1][row] = kv.y;
                    KP[d0+2][row] = kv.z; KP[d0+3][row] = kv.w;
                    *(float4*)&Vs[row][d0] = *(const float4*)&vptr[(row << 6) * DH + d0];
                } else {
                    KP[d0+0][row] = 0.f; KP[d0+1][row] = 0.f;
                    KP[d0+2][row] = 0.f; KP[d0+3][row] = 0.f;
                    *(float4*)&Vs[row][d0] = make_float4(0.f, 0.f, 0.f, 0.f);
                }
            }
            __syncthreads();
            attn_tile_body(Qs, KP, Vs, tx, ty, qt, 0, jmax, true, m, l, acc);
        }

        const int kt0 = (qt >= 2) ? (qt - 2) : 0;
        for (int kt = kt0; kt <= qt; kt++) {
            __syncthreads();
            {
                const int row = tid >> 2;
                const int cc  = tid & 3;
#pragma unroll
                for (int u = 0; u < 4; u++) {
                    const int d0 = (cc + 4 * u) * 4;
                    float4 kv = *(const float4*)&kptr[(kt * 64 + row) * DH + d0];
                    KP[d0+0][row] = kv.x; KP[d0+1][row] = kv.y;
                    KP[d0+2][row] = kv.z; KP[d0+3][row] = kv.w;
                    *(float4*)&Vs[row][d0] = *(const float4*)&vptr[(kt * 64 + row) * DH + d0];
                }
            }
            __syncthreads();
            attn_tile_body(Qs, KP, Vs, tx, ty, qt, kt, 0, false, m, l, acc);
        }

        const int bb = bh >> 4, hh = bh & 15;
#pragma unroll
        for (int i = 0; i < 4; i++) {
            const int q = qt * 64 + ty * 4 + i;
            const float inv = 1.0f / l[i];
            const int idx = (bb * T_SZ + q) * DM + hh * DH + tx * 4;
            *(float4*)&g_attn[idx] = make_float4(acc[i][0]*inv, acc[i][1]*inv,
                                                 acc[i][2]*inv, acc[i][3]*inv);
        }
        return;
    }

    // ---- global-query split-K partials ----
    {
        float (*Qs2)[32] = (float(*)[32])smf;                       // 64 x 32
        float (*KP)[64]  = (float(*)[64])(smf + 64*32);
        float (*Vs)[64]  = (float(*)[64])(smf + 64*32 + 64*64);
        const int id = bid - 2048;
        const int bh = id >> 2;
        const int kc = id & 3;
        const float* qbase = g_q + bh * T_SZ * DH;
        const float* kbase = g_k + bh * T_SZ * DH;
        const float* vbase = g_v + bh * T_SZ * DH;

        {
            const int r  = tid >> 3;
            const int d0 = (tid & 7) * 8;
            float4 q0 = *(const float4*)&qbase[(r << 6) * DH + d0];
            float4 q1 = *(const float4*)&qbase[(r << 6) * DH + d0 + 4];
            Qs2[d0+0][r] = q0.x; Qs2[d0+1][r] = q0.y; Qs2[d0+2][r] = q0.z; Qs2[d0+3][r] = q0.w;
            Qs2[d0+4][r] = q1.x; Qs2[d0+5][r] = q1.y; Qs2[d0+6][r] = q1.z; Qs2[d0+7][r] = q1.w;
        }

        float m[2] = {-1e30f, -1e30f}, l[2] = {0.f, 0.f};
        float acc[2][4];
#pragma unroll
        for (int i = 0; i < 2; i++)
#pragma unroll
            for (int j = 0; j < 4; j++) acc[i][j] = 0.f;

        for (int it = 0; it < 8; it++) {
            const int kt = kc * 8 + it;
            __syncthreads();
            {
                const int row = tid >> 2;
                const int cc  = tid & 3;
#pragma unroll
                for (int u = 0; u < 4; u++) {
                    const int d0 = (cc + 4 * u) * 4;
                    float4 kv = *(const float4*)&kbase[(kt * 64 + row) * DH + d0];
                    KP[d0+0][row] = kv.x; KP[d0+1][row] = kv.y;
                    KP[d0+2][row] = kv.z; KP[d0+3][row] = kv.w;
                    *(float4*)&Vs[row][d0] = *(const float4*)&vbase[(kt * 64 + row) * DH + d0];
                }
            }
            __syncthreads();

            float s[2][4];
#pragma unroll
            for (int i = 0; i < 2; i++)
#pragma unroll
                for (int j = 0; j < 4; j++) s[i][j] = 0.f;
#pragma unroll 16
            for (int d = 0; d < 64; d++) {
                const float a0 = Qs2[d][ty*2];
                const float a1 = Qs2[d][ty*2 + 1];
                float4 b = *(float4*)&KP[d][tx*4];
                float br[4] = {b.x, b.y, b.z, b.w};
#pragma unroll
                for (int j = 0; j < 4; j++) {
                    s[0][j] = fmaf(a0, br[j], s[0][j]);
                    s[1][j] = fmaf(a1, br[j], s[1][j]);
                }
            }
#pragma unroll
            for (int i = 0; i < 2; i++) {
                const int qv = (ty*2 + i) << 6;
#pragma unroll
                for (int j = 0; j < 4; j++) {
                    const int k = kt * 64 + tx*4 + j;
                    s[i][j] = (k <= qv) ? s[i][j] * 0.125f : -1.0e9f;
                }
            }

            float rm[2];
#pragma unroll
            for (int i = 0; i < 2; i++)
                rm[i] = fmaxf(fmaxf(s[i][0], s[i][1]), fmaxf(s[i][2], s[i][3]));
#pragma unroll
            for (int off = 8; off > 0; off >>= 1)
#pragma unroll
                for (int i = 0; i < 2; i++)
                    rm[i] = fmaxf(rm[i], __shfl_xor_sync(0xffffffffu, rm[i], off));

            float sc[2], rs[2];
#pragma unroll
            for (int i = 0; i < 2; i++) {
                const float mn = fmaxf(m[i], rm[i]);
                sc[i] = __expf(m[i] - mn);
                m[i] = mn;
                float r = 0.f;
#pragma unroll
                for (int j = 0; j < 4; j++) {
                    const float p = __expf(s[i][j] - m[i]);
                    s[i][j] = p;
                    r += p;
                }
                rs[i] = r;
            }
#pragma unroll
            for (int off = 8; off > 0; off >>= 1)
#pragma unroll
                for (int i = 0; i < 2; i++)
                    rs[i] += __shfl_xor_sync(0xffffffffu, rs[i], off);
#pragma unroll
            for (int i = 0; i < 2; i++) {
                l[i] = l[i] * sc[i] + rs[i];
#pragma unroll
                for (int j = 0; j < 4; j++) acc[i][j] *= sc[i];
            }

            __syncthreads();
#pragma unroll
            for (int i = 0; i < 2; i++)
                *(float4*)&KP[ty*2 + i][tx*4] = make_float4(s[i][0], s[i][1], s[i][2], s[i][3]);
            __syncthreads();

#pragma unroll 8
            for (int kk = 0; kk < 64; kk += 4) {
                float4 a0 = *(float4*)&KP[ty*2 + 0][kk];
                float4 a1 = *(float4*)&KP[ty*2 + 1][kk];
                float ar[2][4] = {{a0.x,a0.y,a0.z,a0.w},{a1.x,a1.y,a1.z,a1.w}};
#pragma unroll
                for (int u = 0; u < 4; u++) {
                    float4 b = *(float4*)&Vs[kk + u][tx*4];
                    float br[4] = {b.x, b.y, b.z, b.w};
#pragma unroll
                    for (int i = 0; i < 2; i++)
#pragma unroll
                        for (int j = 0; j < 4; j++)
                            acc[i][j] = fmaf(ar[i][u], br[j], acc[i][j]);
                }
            }
        }

        const int base = (bh * 4 + kc) * 32;
#pragma unroll
        for (int i = 0; i < 2; i++) {
            const int r = ty*2 + i;
            *(float4*)&g_pacc[(base + r) * 64 + tx*4] =
                make_float4(acc[i][0], acc[i][1], acc[i][2], acc[i][3]);
            if (tx == 0) { g_pm[base + r] = m[i]; g_pl[base + r] = l[i]; }
        }
    }
}

// ---------------- merge split-K partials ----------------
__global__ __launch_bounds__(256) void attn_gq_combine() {
    const int bh = blockIdx.x;
    const int b = bh >> 4, h = bh & 15;
    for (int idx = threadIdx.x; idx < 32 * 64; idx += 256) {
        const int r = idx >> 6, d = idx & 63;
        float M = -1e30f;
#pragma unroll
        for (int kc = 0; kc < 4; kc++)
            M = fmaxf(M, g_pm[(bh*4 + kc)*32 + r]);
        float l = 0.f, o = 0.f;
#pragma unroll
        for (int kc = 0; kc < 4; kc++) {
            const int p = (bh*4 + kc)*32 + r;
            const float w = __expf(g_pm[p] - M);
            l += w * g_pl[p];
            o += w * g_pacc[p * 64 + d];
        }
        g_attn[(b * T_SZ + (r << 6)) * DM + h * DH + d] = o / l;
    }
}

// ---------------- launch ----------------
extern "C" void kernel_launch(void* const* d_in, const int* in_sizes, int n_in,
                              void* d_out, int out_size) {
    const float *x = 0;
    const float *Wqkv = 0;
    const float *Wout = 0;
    const float *bout = 0;
    for (int i = 0; i < n_in; i++) {
        switch (in_sizes[i]) {
            case B_SZ*T_SZ*DM: x    = (const float*)d_in[i]; break;
            case DM*3*DM:      Wqkv = (const float*)d_in[i]; break;
            case DM*DM:        Wout = (const float*)d_in[i]; break;
            case DM:           bout = (const float*)d_in[i]; break;
        }
    }
    float* out = (float*)d_out;

    cudaFuncSetAttribute(qkv_tc_kernel, cudaFuncAttributeMaxDynamicSharedMemorySize, GEMM_SMEM);
    cudaFuncSetAttribute(out_tc_kernel, cudaFuncAttributeMaxDynamicSharedMemorySize, GEMM_SMEM);

    __nv_bfloat16 *xh, *xl, *wqh, *wql, *woh, *wol, *ah, *al;
    float* attn_f;
    cudaGetSymbolAddress((void**)&xh,  g_xh);
    cudaGetSymbolAddress((void**)&xl,  g_xl);
    cudaGetSymbolAddress((void**)&wqh, g_wqh);
    cudaGetSymbolAddress((void**)&wql, g_wql);
    cudaGetSymbolAddress((void**)&woh, g_woh);
    cudaGetSymbolAddress((void**)&wol, g_wol);
    cudaGetSymbolAddress((void**)&ah,  g_ah);
    cudaGetSymbolAddress((void**)&al,  g_al);
    cudaGetSymbolAddress((void**)&attn_f, g_attn);

    rope_table_kernel<<<(T_SZ*HALF + 255) / 256, 256>>>();
    cvt_split_kernel<<<(B_SZ*T_SZ*DM/4 + 255) / 256, 256>>>(x, xh, xl, B_SZ*T_SZ*DM/4);
    cvt_split_kernel<<<(DM*3*DM/4 + 255) / 256, 256>>>(Wqkv, wqh, wql, DM*3*DM/4);
    cvt_split_kernel<<<(DM*DM/4 + 255) / 256, 256>>>(Wout, woh, wol, DM*DM/4);

    qkv_tc_kernel<<<dim3(3*DM/128, B_SZ*T_SZ/128), 512, GEMM_SMEM>>>();
    attn_fused_kernel<<<2048 + 256, 256, 48*1024>>>();
    attn_gq_combine<<<B_SZ*NH, 256>>>();
    cvt_split_kernel<<<(B_SZ*T_SZ*DM/4 + 255) / 256, 256>>>(attn_f, ah, al, B_SZ*T_SZ*DM/4);
    out_tc_kernel<<<dim3(DM/128, B_SZ*T_SZ/128), 512, GEMM_SMEM>>>(bout, out);
}

// round 12
// speedup vs baseline: 1.0607x; 1.0607x over previous
#include <cuda_runtime.h>
#include <cuda_bf16.h>
#include <math.h>

#define B_SZ 4
#define T_SZ 2048
#define DM   1024
#define NH   16
#define DH   64
#define HALF 32   // DH/2

typedef unsigned int u32;

// ---------------- scratch (device globals; no runtime allocation) ----------------
__device__ float g_q[B_SZ*NH*T_SZ*DH];
__device__ float g_k[B_SZ*NH*T_SZ*DH];
__device__ float g_v[B_SZ*NH*T_SZ*DH];
__device__ float g_attn[B_SZ*T_SZ*DM];
__device__ float g_cos[T_SZ*HALF];
__device__ float g_sin[T_SZ*HALF];
__device__ float g_pm[64*4*32];
__device__ float g_pl[64*4*32];
__device__ float g_pacc[64*4*32*64];
// pre-converted bf16 hi/lo operands
__device__ __nv_bfloat16 g_xh[B_SZ*T_SZ*DM];
__device__ __nv_bfloat16 g_xl[B_SZ*T_SZ*DM];
__device__ __nv_bfloat16 g_wqh[DM*3*DM];
__device__ __nv_bfloat16 g_wql[DM*3*DM];
__device__ __nv_bfloat16 g_woh[DM*DM];
__device__ __nv_bfloat16 g_wol[DM*DM];
__device__ __nv_bfloat16 g_ah[B_SZ*T_SZ*DM];
__device__ __nv_bfloat16 g_al[B_SZ*T_SZ*DM];

// ---------------- GEMM tiling constants ----------------
#define KS        16          // k-step (bf16 elems)
#define NSTG      4
// A: 128 rows x 24 bf16 (48B) per buffer; B: 16 rows x 136 bf16 (272B)
#define AH_OFF    0           // 128*48 = 6144
#define AL_OFF    6144
#define BH_OFF    12288       // 16*272 = 4352
#define BL_OFF    16640
#define STG_BYTES 20992
#define GEMM_SMEM (NSTG * STG_BYTES)   // 83968 -> 2 CTAs/SM

// ---------------- tensor-core / async helpers ----------------
__device__ __forceinline__ void ldsm4(u32& r0, u32& r1, u32& r2, u32& r3, u32 a) {
    asm volatile("ldmatrix.sync.aligned.m8n8.x4.shared.b16 {%0,%1,%2,%3}, [%4];"
                 : "=r"(r0), "=r"(r1), "=r"(r2), "=r"(r3) : "r"(a));
}
__device__ __forceinline__ void ldsm4t(u32& r0, u32& r1, u32& r2, u32& r3, u32 a) {
    asm volatile("ldmatrix.sync.aligned.m8n8.x4.trans.shared.b16 {%0,%1,%2,%3}, [%4];"
                 : "=r"(r0), "=r"(r1), "=r"(r2), "=r"(r3) : "r"(a));
}
__device__ __forceinline__ void mma_bf16(float* d, const u32* a, const u32* b) {
    asm volatile("mma.sync.aligned.m16n8k16.row.col.f32.bf16.bf16.f32 "
                 "{%0,%1,%2,%3}, {%4,%5,%6,%7}, {%8,%9}, {%0,%1,%2,%3};"
                 : "+f"(d[0]), "+f"(d[1]), "+f"(d[2]), "+f"(d[3])
                 : "r"(a[0]), "r"(a[1]), "r"(a[2]), "r"(a[3]), "r"(b[0]), "r"(b[1]));
}
__device__ __forceinline__ void cpa16(u32 dst, const void* src) {
    asm volatile("cp.async.cg.shared.global [%0], [%1], 16;" :: "r"(dst), "l"(src) : "memory");
}
__device__ __forceinline__ void cpa_commit() {
    asm volatile("cp.async.commit_group;" ::: "memory");
}
template<int N> __device__ __forceinline__ void cpa_wait() {
    asm volatile("cp.async.wait_group %0;" :: "n"(N) : "memory");
}

// ---------------- cvt kernel ----------------
__global__ void cvt_split_kernel(const float* __restrict__ src,
                                 __nv_bfloat16* __restrict__ hi,
                                 __nv_bfloat16* __restrict__ lo, int n4) {
    int i = blockIdx.x * blockDim.x + threadIdx.x;
    if (i >= n4) return;
    float4 v = ((const float4*)src)[i];
    float vv[4] = {v.x, v.y, v.z, v.w};
    u32 hw[2];
    u32 lw[2];
#pragma unroll
    for (int p = 0; p < 2; p++) {
        __nv_bfloat16 h0 = __float2bfloat16(vv[2*p]);
        __nv_bfloat16 h1 = __float2bfloat16(vv[2*p+1]);
        __nv_bfloat16 l0 = __float2bfloat16(vv[2*p]   - __bfloat162float(h0));
        __nv_bfloat16 l1 = __float2bfloat16(vv[2*p+1] - __bfloat162float(h1));
        __nv_bfloat162 hp = __halves2bfloat162(h0, h1);
        __nv_bfloat162 lp = __halves2bfloat162(l0, l1);
        hw[p] = *(u32*)&hp;
        lw[p] = *(u32*)&lp;
    }
    ((uint2*)hi)[i] = make_uint2(hw[0], hw[1]);
    ((uint2*)lo)[i] = make_uint2(lw[0], lw[1]);
}

// ---------------- kernel 0: RoPE tables ----------------
__global__ void rope_table_kernel() {
    int idx = blockIdx.x * blockDim.x + threadIdx.x;
    if (idx >= T_SZ * HALF) return;
    int t = idx / HALF;
    int j = idx % HALF;
    double inv = pow(10000.0, -(double)j / (double)HALF);
    double ang = (double)t * inv;
    g_cos[idx] = (float)cos(ang);
    g_sin[idx] = (float)sin(ang);
}

// ---------------- 128x128 bf16-split GEMM, 256 thr, KS=16, 4-stage, 2 CTA/SM ----
// 8 warps in 2x4 grid; warp tile 64x32 (mi 4 x ni 4 m16n8 frags).
template<int LDB>
__device__ __forceinline__ void tc_gemm_bf16(
    const __nv_bfloat16* __restrict__ Ahg, const __nv_bfloat16* __restrict__ Alg,
    const __nv_bfloat16* __restrict__ Bhg, const __nv_bfloat16* __restrict__ Blg,
    float (&acc)[4][4][4])
{
    extern __shared__ char sm[];
    const u32 smb = (u32)__cvta_generic_to_shared(sm);
    const int tid  = threadIdx.x;
    const int lane = tid & 31;
    const int warp = tid >> 5;            // 0..7
    const int wm = warp >> 2;             // 0..1
    const int wn = warp & 3;              // 0..3
    const int arow = (lane & 7) + ((lane >> 3) & 1) * 8;   // 0..15
    const int akk  = ((lane >> 4) & 1) * 8;                // 0 or 8 elems

    const int ar = tid >> 1;              // A row 0..127
    const int ac = (tid & 1) * 8;         // A elem chunk (8 elems = 16B)
    const int br = tid >> 4;              // B k-row 0..15
    const int bc = (tid & 15) * 8;        // B col chunk

#pragma unroll
    for (int mi = 0; mi < 4; mi++)
#pragma unroll
        for (int ni = 0; ni < 4; ni++)
#pragma unroll
            for (int r = 0; r < 4; r++)
                acc[mi][ni][r] = 0.f;

    const u32 a_soff = (u32)(ar * 48 + ac * 2);
    const u32 b_soff = (u32)(br * 272 + bc * 2);

#define ISSUE_STAGE(kt, st) do {                                                   \
        const u32 sb = smb + (u32)(st) * STG_BYTES;                                \
        cpa16(sb + AH_OFF + a_soff, Ahg + (size_t)ar * DM + (kt) * KS + ac);       \
        cpa16(sb + AL_OFF + a_soff, Alg + (size_t)ar * DM + (kt) * KS + ac);       \
        cpa16(sb + BH_OFF + b_soff, Bhg + (size_t)((kt) * KS + br) * LDB + bc);    \
        cpa16(sb + BL_OFF + b_soff, Blg + (size_t)((kt) * KS + br) * LDB + bc);    \
        cpa_commit();                                                              \
    } while (0)

    ISSUE_STAGE(0, 0);
    ISSUE_STAGE(1, 1);
    ISSUE_STAGE(2, 2);

    const int KT = DM / KS;               // 64
    for (int kt = 0; kt < KT; kt++) {
        if (kt < KT - 2)      cpa_wait<2>();
        else if (kt == KT - 2) cpa_wait<1>();
        else                   cpa_wait<0>();
        __syncthreads();
        if (kt + 3 < KT) ISSUE_STAGE(kt + 3, (kt + 3) & 3);

        const u32 sb = smb + (u32)(kt & 3) * STG_BYTES;
        const u32 abase = sb + (u32)((wm*64 + arow) * 48 + akk * 2);
        const u32 bbase = sb + BH_OFF + (u32)(arow * 272 + (wn*32 + akk) * 2);

        u32 AH[4][4];
        u32 BH[4][2];
        u32 BL[4][2];
#pragma unroll
        for (int mi = 0; mi < 4; mi++)
            ldsm4(AH[mi][0], AH[mi][1], AH[mi][2], AH[mi][3],
                  abase + AH_OFF + (u32)(mi * 16 * 48));
#pragma unroll
        for (int nj = 0; nj < 2; nj++) {
            u32 t0, t1, t2, t3;
            ldsm4t(t0, t1, t2, t3, bbase + (u32)(nj * 32));
            BH[nj*2][0] = t0;
            BH[nj*2][1] = t1;
            BH[nj*2+1][0] = t2;
            BH[nj*2+1][1] = t3;
            ldsm4t(t0, t1, t2, t3, bbase + (u32)(BL_OFF - BH_OFF + nj * 32));
            BL[nj*2][0] = t0;
            BL[nj*2][1] = t1;
            BL[nj*2+1][0] = t2;
            BL[nj*2+1][1] = t3;
        }
        // AH x (BH, BL) first; AL loaded after AH's last use to cap live regs
#pragma unroll
        for (int mi = 0; mi < 4; mi++) {
#pragma unroll
            for (int ni = 0; ni < 4; ni++) {
                mma_bf16(acc[mi][ni], AH[mi], BH[ni]);
                mma_bf16(acc[mi][ni], AH[mi], BL[ni]);
            }
        }
#pragma unroll
        for (int mi = 0; mi < 4; mi++) {
            u32 AL[4];
            ldsm4(AL[0], AL[1], AL[2], AL[3], abase + AL_OFF + (u32)(mi * 16 * 48));
#pragma unroll
            for (int ni = 0; ni < 4; ni++)
                mma_bf16(acc[mi][ni], AL, BH[ni]);
        }
    }
#undef ISSUE_STAGE
}

// ---------------- kernel 1: QKV GEMM + RoPE epilogue ----------------
__global__ __launch_bounds__(256, 2) void qkv_tc_kernel() {
    const int row0 = blockIdx.y * 128;
    const int col0 = blockIdx.x * 128;
    float acc[4][4][4];
    tc_gemm_bf16<3072>(g_xh + (size_t)row0 * DM, g_xl + (size_t)row0 * DM,
                       g_wqh + col0, g_wql + col0, acc);

    const int lane = threadIdx.x & 31;
    const int warp = threadIdx.x >> 5;
    const int wm = warp >> 2;
    const int wn = warp & 3;
    const int r0c = lane >> 2;
    const int cp  = (lane & 3) * 2;
    const int which = col0 >> 10;                      // 0=q 1=k 2=v
    float* dst = (which == 0) ? g_q : ((which == 1) ? g_k : g_v);
    const bool dorope = (which < 2);

#pragma unroll
    for (int mi = 0; mi < 4; mi++) {
#pragma unroll
        for (int half = 0; half < 2; half++) {
            const int gm = row0 + wm*64 + mi*16 + r0c + half*8;
            const int bb = gm >> 11;
            const int t  = gm & (T_SZ - 1);
#pragma unroll
            for (int ni = 0; ni < 4; ni++) {
                const int gn  = col0 + wn*32 + ni*8 + cp;
                const int rem = gn & 1023;
                const int h = rem >> 6;
                const int d = rem & 63;
                float v0 = acc[mi][ni][half*2 + 0];
                float v1 = acc[mi][ni][half*2 + 1];
                if (dorope) {
                    const int j = d >> 1;
                    const float c = g_cos[t*HALF + j];
                    const float s = g_sin[t*HALF + j];
                    const float re = v0*c - v1*s;
                    const float ro = v0*s + v1*c;
                    v0 = re;
                    v1 = ro;
                }
                *(float2*)&dst[((size_t)(bb*NH + h) * T_SZ + t) * DH + d] = make_float2(v0, v1);
            }
        }
    }
}

// ---------------- kernel 3: out projection + bias ----------------
__global__ __launch_bounds__(256, 2) void out_tc_kernel(const float* __restrict__ bias,
                                                        float* __restrict__ out) {
    const int row0 = blockIdx.y * 128;
    const int col0 = blockIdx.x * 128;
    float acc[4][4][4];
    tc_gemm_bf16<1024>(g_ah + (size_t)row0 * DM, g_al + (size_t)row0 * DM,
                       g_woh + col0, g_wol + col0, acc);

    const int lane = threadIdx.x & 31;
    const int warp = threadIdx.x >> 5;
    const int wm = warp >> 2;
    const int wn = warp & 3;
    const int r0c = lane >> 2;
    const int cp  = (lane & 3) * 2;

#pragma unroll
    for (int mi = 0; mi < 4; mi++) {
#pragma unroll
        for (int half = 0; half < 2; half++) {
            const int gm = row0 + wm*64 + mi*16 + r0c + half*8;
#pragma unroll
            for (int ni = 0; ni < 4; ni++) {
                const int gn = col0 + wn*32 + ni*8 + cp;
                const float b0 = bias[gn];
                const float b1 = bias[gn + 1];
                *(float2*)&out[(size_t)gm * DM + gn] =
                    make_float2(acc[mi][ni][half*2 + 0] + b0,
                                acc[mi][ni][half*2 + 1] + b1);
            }
        }
    }
}

// ---------------- shared attention tile body (pointer form) ----------------
__device__ __forceinline__ void attn_tile_body(
    float (*Qs)[64], float (*KP)[64], float (*Vs)[64],
    int tx, int ty, int qt, int kt, int jmax, bool global_tile,
    float (&m)[4], float (&l)[4], float (&acc)[4][4])
{
    float s[4][4];
#pragma unroll
    for (int i = 0; i < 4; i++)
#pragma unroll
        for (int j = 0; j < 4; j++) s[i][j] = 0.f;
#pragma unroll 16
    for (int d = 0; d < 64; d++) {
        float4 a = *(float4*)&Qs[d][ty*4];
        float4 b = *(float4*)&KP[d][tx*4];
        float ar[4] = {a.x, a.y, a.z, a.w};
        float br[4] = {b.x, b.y, b.z, b.w};
#pragma unroll
        for (int i = 0; i < 4; i++)
#pragma unroll
            for (int j = 0; j < 4; j++)
                s[i][j] = fmaf(ar[i], br[j], s[i][j]);
    }

    if (global_tile) {
#pragma unroll
        for (int i = 0; i < 4; i++)
#pragma unroll
            for (int j = 0; j < 4; j++) {
                const bool ok = (tx*4 + j) <= jmax;
                s[i][j] = ok ? s[i][j] * 0.125f : -1.0e9f;
            }
    } else {
        const int qb = qt * 64 + ty * 4;
        const int kb = kt * 64 + tx * 4;
#pragma unroll
        for (int i = 0; i < 4; i++) {
            const int q = qb + i;
            const bool qg = ((q & 63) == 0);
#pragma unroll
            for (int j = 0; j < 4; j++) {
                const int k = kb + j;
                const bool ok = (k <= q) && ((q - k) <= 127 || ((k & 63) == 0) || qg);
                s[i][j] = ok ? s[i][j] * 0.125f : -1.0e9f;
            }
        }
    }

    float rm[4];
#pragma unroll
    for (int i = 0; i < 4; i++)
        rm[i] = fmaxf(fmaxf(s[i][0], s[i][1]), fmaxf(s[i][2], s[i][3]));
#pragma unroll
    for (int off = 8; off > 0; off >>= 1)
#pragma unroll
        for (int i = 0; i < 4; i++)
            rm[i] = fmaxf(rm[i], __shfl_xor_sync(0xffffffffu, rm[i], off));

    float sc[4];
#pragma unroll
    for (int i = 0; i < 4; i++) {
        const float mn = fmaxf(m[i], rm[i]);
        sc[i] = __expf(m[i] - mn);
        m[i] = mn;
    }
    float rs[4];
#pragma unroll
    for (int i = 0; i < 4; i++) {
        float r = 0.f;
#pragma unroll
        for (int j = 0; j < 4; j++) {
            const float p = __expf(s[i][j] - m[i]);
            s[i][j] = p;
            r += p;
        }
        rs[i] = r;
    }
#pragma unroll
    for (int off = 8; off > 0; off >>= 1)
#pragma unroll
        for (int i = 0; i < 4; i++)
            rs[i] += __shfl_xor_sync(0xffffffffu, rs[i], off);
#pragma unroll
    for (int i = 0; i < 4; i++) {
        l[i] = l[i] * sc[i] + rs[i];
#pragma unroll
        for (int j = 0; j < 4; j++) acc[i][j] *= sc[i];
    }

    __syncthreads();
#pragma unroll
    for (int i = 0; i < 4; i++)
        *(float4*)&KP[ty*4 + i][tx*4] = make_float4(s[i][0], s[i][1], s[i][2], s[i][3]);
    __syncthreads();

#pragma unroll 8
    for (int kk = 0; kk < 64; kk += 4) {
        float4 a0 = *(float4*)&KP[ty*4 + 0][kk];
        float4 a1 = *(float4*)&KP[ty*4 + 1][kk];
        float4 a2 = *(float4*)&KP[ty*4 + 2][kk];
        float4 a3 = *(float4*)&KP[ty*4 + 3][kk];
        float ar[4][4] = {{a0.x,a0.y,a0.z,a0.w},{a1.x,a1.y,a1.z,a1.w},
                          {a2.x,a2.y,a2.z,a2.w},{a3.x,a3.y,a3.z,a3.w}};
#pragma unroll
        for (int u = 0; u < 4; u++) {
            float4 b = *(float4*)&Vs[kk + u][tx*4];
            float br[4] = {b.x, b.y, b.z, b.w};
#pragma unroll
            for (int i = 0; i < 4; i++)
#pragma unroll
                for (int j = 0; j < 4; j++)
                    acc[i][j] = fmaf(ar[i][u], br[j], acc[i][j]);
        }
    }
}

// ---------------- fused attention: main sparse flash + global-query partials ----
__global__ __launch_bounds__(256) void attn_fused_kernel() {
    extern __shared__ float smf[];
    const int bid = blockIdx.x;
    const int tid = threadIdx.x;
    const int tx = tid & 15, ty = tid >> 4;

    if (bid < 2048) {
        float (*Qs)[64] = (float(*)[64])smf;
        float (*KP)[64] = (float(*)[64])(smf + 64*64);
        float (*Vs)[64] = (float(*)[64])(smf + 2*64*64);
        const int qt = bid & 31;
        const int bh = bid >> 5;
        const float* qptr = g_q + (bh * T_SZ + qt * 64) * DH;
        const float* kptr = g_k + bh * T_SZ * DH;
        const float* vptr = g_v + bh * T_SZ * DH;

        {
            const int row = tid >> 2;
            const int cc  = tid & 3;
#pragma unroll
            for (int u = 0; u < 4; u++) {
                const int d0 = (cc + 4 * u) * 4;
                float4 qv = *(const float4*)&qptr[row * DH + d0];
                Qs[d0+0][row] = qv.x; Qs[d0+1][row] = qv.y;
                Qs[d0+2][row] = qv.z; Qs[d0+3][row] = qv.w;
            }
        }

        float m[4], l[4], acc[4][4];
#pragma unroll
        for (int i = 0; i < 4; i++) {
            m[i] = -1e30f; l[i] = 0.f;
#pragma unroll
            for (int j = 0; j < 4; j++) acc[i][j] = 0.f;
        }

        if (qt >= 3) {
            const int jmax = qt - 3;
            const int row = tid >> 2;
            const int cc  = tid & 3;
            const bool valid = (row <= jmax);
#pragma unroll
            for (int u = 0; u < 4; u++) {
                const int d0 = (cc + 4 * u) * 4;
                if (valid) {
                    float4 kv = *(const float4*)&kptr[(row << 6) * DH + d0];
                    KP[d0+0][row] = kv.x; KP[d0+1][row] = kv.y;
                    KP[d0+2][row] = kv.z; KP[d0+3][row] = kv.w;
                    *(float4*)&Vs[row][d0] = *(const float4*)&vptr[(row << 6) * DH + d0];
                } else {
                    KP[d0+0][row] = 0.f; KP[d0+1][row] = 0.f;
                    KP[d0+2][row] = 0.f; KP[d0+3][row] = 0.f;
                    *(float4*)&Vs[row][d0] = make_float4(0.f, 0.f, 0.f, 0.f);
                }
            }
            __syncthreads();
            attn_tile_body(Qs, KP, Vs, tx, ty, qt, 0, jmax, true, m, l, acc);
        }

        const int kt0 = (qt >= 2) ? (qt - 2) : 0;
        for (int kt = kt0; kt <= qt; kt++) {
            __syncthreads();
            {
                const int row = tid >> 2;
                const int cc  = tid & 3;
#pragma unroll
                for (int u = 0; u < 4; u++) {
                    const int d0 = (cc + 4 * u) * 4;
                    float4 kv = *(const float4*)&kptr[(kt * 64 + row) * DH + d0];
                    KP[d0+0][row] = kv.x; KP[d0+1][row] = kv.y;
                    KP[d0+2][row] = kv.z; KP[d0+3][row] = kv.w;
                    *(float4*)&Vs[row][d0] = *(const float4*)&vptr[(kt * 64 + row) * DH + d0];
                }
            }
            __syncthreads();
            attn_tile_body(Qs, KP, Vs, tx, ty, qt, kt, 0, false, m, l, acc);
        }

        const int bb = bh >> 4, hh = bh & 15;
#pragma unroll
        for (int i = 0; i < 4; i++) {
            const int q = qt * 64 + ty * 4 + i;
            const float inv = 1.0f / l[i];
            const int idx = (bb * T_SZ + q) * DM + hh * DH + tx * 4;
            *(float4*)&g_attn[idx] = make_float4(acc[i][0]*inv, acc[i][1]*inv,
                                                 acc[i][2]*inv, acc[i][3]*inv);
        }
        return;
    }

    // ---- global-query split-K partials ----
    {
        float (*Qs2)[32] = (float(*)[32])smf;
        float (*KP)[64]  = (float(*)[64])(smf + 64*32);
        float (*Vs)[64]  = (float(*)[64])(smf + 64*32 + 64*64);
        const int id = bid - 2048;
        const int bh = id >> 2;
        const int kc = id & 3;
        const float* qbase = g_q + bh * T_SZ * DH;
        const float* kbase = g_k + bh * T_SZ * DH;
        const float* vbase = g_v + bh * T_SZ * DH;

        {
            const int r  = tid >> 3;
            const int d0 = (tid & 7) * 8;
            float4 q0 = *(const float4*)&qbase[(r << 6) * DH + d0];
            float4 q1 = *(const float4*)&qbase[(r << 6) * DH + d0 + 4];
            Qs2[d0+0][r] = q0.x; Qs2[d0+1][r] = q0.y; Qs2[d0+2][r] = q0.z; Qs2[d0+3][r] = q0.w;
            Qs2[d0+4][r] = q1.x; Qs2[d0+5][r] = q1.y; Qs2[d0+6][r] = q1.z; Qs2[d0+7][r] = q1.w;
        }

        float m[2] = {-1e30f, -1e30f}, l[2] = {0.f, 0.f};
        float acc[2][4];
#pragma unroll
        for (int i = 0; i < 2; i++)
#pragma unroll
            for (int j = 0; j < 4; j++) acc[i][j] = 0.f;

        for (int it = 0; it < 8; it++) {
            const int kt = kc * 8 + it;
            __syncthreads();
            {
                const int row = tid >> 2;
                const int cc  = tid & 3;
#pragma unroll
                for (int u = 0; u < 4; u++) {
                    const int d0 = (cc + 4 * u) * 4;
                    float4 kv = *(const float4*)&kbase[(kt * 64 + row) * DH + d0];
                    KP[d0+0][row] = kv.x; KP[d0+1][row] = kv.y;
                    KP[d0+2][row] = kv.z; KP[d0+3][row] = kv.w;
                    *(float4*)&Vs[row][d0] = *(const float4*)&vbase[(kt * 64 + row) * DH + d0];
                }
            }
            __syncthreads();

            float s[2][4];
#pragma unroll
            for (int i = 0; i < 2; i++)
#pragma unroll
                for (int j = 0; j < 4; j++) s[i][j] = 0.f;
#pragma unroll 16
            for (int d = 0; d < 64; d++) {
                const float a0 = Qs2[d][ty*2];
                const float a1 = Qs2[d][ty*2 + 1];
                float4 b = *(float4*)&KP[d][tx*4];
                float br[4] = {b.x, b.y, b.z, b.w};
#pragma unroll
                for (int j = 0; j < 4; j++) {
                    s[0][j] = fmaf(a0, br[j], s[0][j]);
                    s[1][j] = fmaf(a1, br[j], s[1][j]);
                }
            }
#pragma unroll
            for (int i = 0; i < 2; i++) {
                const int qv = (ty*2 + i) << 6;
#pragma unroll
                for (int j = 0; j < 4; j++) {
                    const int k = kt * 64 + tx*4 + j;
                    s[i][j] = (k <= qv) ? s[i][j] * 0.125f : -1.0e9f;
                }
            }

            float rm[2];
#pragma unroll
            for (int i = 0; i < 2; i++)
                rm[i] = fmaxf(fmaxf(s[i][0], s[i][1]), fmaxf(s[i][2], s[i][3]));
#pragma unroll
            for (int off = 8; off > 0; off >>= 1)
#pragma unroll
                for (int i = 0; i < 2; i++)
                    rm[i] = fmaxf(rm[i], __shfl_xor_sync(0xffffffffu, rm[i], off));

            float sc[2], rs[2];
#pragma unroll
            for (int i = 0; i < 2; i++) {
                const float mn = fmaxf(m[i], rm[i]);
                sc[i] = __expf(m[i] - mn);
                m[i] = mn;
                float r = 0.f;
#pragma unroll
                for (int j = 0; j < 4; j++) {
                    const float p = __expf(s[i][j] - m[i]);
                    s[i][j] = p;
                    r += p;
                }
                rs[i] = r;
            }
#pragma unroll
            for (int off = 8; off > 0; off >>= 1)
#pragma unroll
                for (int i = 0; i < 2; i++)
                    rs[i] += __shfl_xor_sync(0xffffffffu, rs[i], off);
#pragma unroll
            for (int i = 0; i < 2; i++) {
                l[i] = l[i] * sc[i] + rs[i];
#pragma unroll
                for (int j = 0; j < 4; j++) acc[i][j] *= sc[i];
            }

            __syncthreads();
#pragma unroll
            for (int i = 0; i < 2; i++)
                *(float4*)&KP[ty*2 + i][tx*4] = make_float4(s[i][0], s[i][1], s[i][2], s[i][3]);
            __syncthreads();

#pragma unroll 8
            for (int kk = 0; kk < 64; kk += 4) {
                float4 a0 = *(float4*)&KP[ty*2 + 0][kk];
                float4 a1 = *(float4*)&KP[ty*2 + 1][kk];
                float ar[2][4] = {{a0.x,a0.y,a0.z,a0.w},{a1.x,a1.y,a1.z,a1.w}};
#pragma unroll
                for (int u = 0; u < 4; u++) {
                    float4 b = *(float4*)&Vs[kk + u][tx*4];
                    float br[4] = {b.x, b.y, b.z, b.w};
#pragma unroll
                    for (int i = 0; i < 2; i++)
#pragma unroll
                        for (int j = 0; j < 4; j++)
                            acc[i][j] = fmaf(ar[i][u], br[j], acc[i][j]);
                }
            }
        }

        const int base = (bh * 4 + kc) * 32;
#pragma unroll
        for (int i = 0; i < 2; i++) {
            const int r = ty*2 + i;
            *(float4*)&g_pacc[(base + r) * 64 + tx*4] =
                make_float4(acc[i][0], acc[i][1], acc[i][2], acc[i][3]);
            if (tx == 0) { g_pm[base + r] = m[i]; g_pl[base + r] = l[i]; }
        }
    }
}

// ---------------- merge split-K partials ----------------
__global__ __launch_bounds__(256) void attn_gq_combine() {
    const int bh = blockIdx.x;
    const int b = bh >> 4, h = bh & 15;
    for (int idx = threadIdx.x; idx < 32 * 64; idx += 256) {
        const int r = idx >> 6, d = idx & 63;
        float M = -1e30f;
#pragma unroll
        for (int kc = 0; kc < 4; kc++)
            M = fmaxf(M, g_pm[(bh*4 + kc)*32 + r]);
        float l = 0.f, o = 0.f;
#pragma unroll
        for (int kc = 0; kc < 4; kc++) {
            const int p = (bh*4 + kc)*32 + r;
            const float w = __expf(g_pm[p] - M);
            l += w * g_pl[p];
            o += w * g_pacc[p * 64 + d];
        }
        g_attn[(b * T_SZ + (r << 6)) * DM + h * DH + d] = o / l;
    }
}

// ---------------- launch ----------------
extern "C" void kernel_launch(void* const* d_in, const int* in_sizes, int n_in,
                              void* d_out, int out_size) {
    const float *x = 0;
    const float *Wqkv = 0;
    const float *Wout = 0;
    const float *bout = 0;
    for (int i = 0; i < n_in; i++) {
        switch (in_sizes[i]) {
            case B_SZ*T_SZ*DM: x    = (const float*)d_in[i]; break;
            case DM*3*DM:      Wqkv = (const float*)d_in[i]; break;
            case DM*DM:        Wout = (const float*)d_in[i]; break;
            case DM:           bout = (const float*)d_in[i]; break;
        }
    }
    float* out = (float*)d_out;

    cudaFuncSetAttribute(qkv_tc_kernel, cudaFuncAttributeMaxDynamicSharedMemorySize, GEMM_SMEM);
    cudaFuncSetAttribute(out_tc_kernel, cudaFuncAttributeMaxDynamicSharedMemorySize, GEMM_SMEM);

    __nv_bfloat16 *xh, *xl, *wqh, *wql, *woh, *wol, *ah, *al;
    float* attn_f;
    cudaGetSymbolAddress((void**)&xh,  g_xh);
    cudaGetSymbolAddress((void**)&xl,  g_xl);
    cudaGetSymbolAddress((void**)&wqh, g_wqh);
    cudaGetSymbolAddress((void**)&wql, g_wql);
    cudaGetSymbolAddress((void**)&woh, g_woh);
    cudaGetSymbolAddress((void**)&wol, g_wol);
    cudaGetSymbolAddress((void**)&ah,  g_ah);
    cudaGetSymbolAddress((void**)&al,  g_al);
    cudaGetSymbolAddress((void**)&attn_f, g_attn);

    rope_table_kernel<<<(T_SZ*HALF + 255) / 256, 256>>>();
    cvt_split_kernel<<<(B_SZ*T_SZ*DM/4 + 255) / 256, 256>>>(x, xh, xl, B_SZ*T_SZ*DM/4);
    cvt_split_kernel<<<(DM*3*DM/4 + 255) / 256, 256>>>(Wqkv, wqh, wql, DM*3*DM/4);
    cvt_split_kernel<<<(DM*DM/4 + 255) / 256, 256>>>(Wout, woh, wol, DM*DM/4);

    qkv_tc_kernel<<<dim3(3*DM/128, B_SZ*T_SZ/128), 256, GEMM_SMEM>>>();
    attn_fused_kernel<<<2048 + 256, 256, 48*1024>>>();
    attn_gq_combine<<<B_SZ*NH, 256>>>();
    cvt_split_kernel<<<(B_SZ*T_SZ*DM/4 + 255) / 256, 256>>>(attn_f, ah, al, B_SZ*T_SZ*DM/4);
    out_tc_kernel<<<dim3(DM/128, B_SZ*T_SZ/128), 256, GEMM_SMEM>>>(bout, out);
}

// round 13
// speedup vs baseline: 1.7496x; 1.6496x over previous
#include <cuda_runtime.h>
#include <cuda_fp16.h>
#include <math.h>

#define B_SZ 4
#define T_SZ 2048
#define DM   1024
#define NH   16
#define DH   64
#define HALF 32   // DH/2

typedef unsigned int u32;

// ---------------- scratch (device globals; no runtime allocation) ----------------
__device__ float g_q[B_SZ*NH*T_SZ*DH];
__device__ float g_k[B_SZ*NH*T_SZ*DH];
__device__ float g_v[B_SZ*NH*T_SZ*DH];
__device__ float g_attn[B_SZ*T_SZ*DM];
__device__ float g_cos[T_SZ*HALF];
__device__ float g_sin[T_SZ*HALF];
__device__ float g_pm[64*4*32];
__device__ float g_pl[64*4*32];
__device__ float g_pacc[64*4*32*64];
// pre-converted fp16 operands
__device__ __half g_xh[B_SZ*T_SZ*DM];
__device__ __half g_wqh[DM*3*DM];
__device__ __half g_woh[DM*DM];
__device__ __half g_ah[B_SZ*T_SZ*DM];

// ---------------- GEMM tiling constants ----------------
#define KS        16          // k-step (fp16 elems)
#define NSTG      4
// A: 128 rows x 24 fp16 (48B); B: 16 rows x 136 fp16 (272B)
#define A_OFF     0           // 128*48 = 6144
#define B_OFF     6144        // 16*272 = 4352
#define STG_BYTES 10496
#define GEMM_SMEM (NSTG * STG_BYTES)   // 41984

// ---------------- tensor-core / async helpers ----------------
__device__ __forceinline__ void ldsm4(u32& r0, u32& r1, u32& r2, u32& r3, u32 a) {
    asm volatile("ldmatrix.sync.aligned.m8n8.x4.shared.b16 {%0,%1,%2,%3}, [%4];"
                 : "=r"(r0), "=r"(r1), "=r"(r2), "=r"(r3) : "r"(a));
}
__device__ __forceinline__ void ldsm4t(u32& r0, u32& r1, u32& r2, u32& r3, u32 a) {
    asm volatile("ldmatrix.sync.aligned.m8n8.x4.trans.shared.b16 {%0,%1,%2,%3}, [%4];"
                 : "=r"(r0), "=r"(r1), "=r"(r2), "=r"(r3) : "r"(a));
}
__device__ __forceinline__ void mma_f16(float* d, const u32* a, const u32* b) {
    asm volatile("mma.sync.aligned.m16n8k16.row.col.f32.f16.f16.f32 "
                 "{%0,%1,%2,%3}, {%4,%5,%6,%7}, {%8,%9}, {%0,%1,%2,%3};"
                 : "+f"(d[0]), "+f"(d[1]), "+f"(d[2]), "+f"(d[3])
                 : "r"(a[0]), "r"(a[1]), "r"(a[2]), "r"(a[3]), "r"(b[0]), "r"(b[1]));
}
__device__ __forceinline__ void cpa16(u32 dst, const void* src) {
    asm volatile("cp.async.cg.shared.global [%0], [%1], 16;" :: "r"(dst), "l"(src) : "memory");
}
__device__ __forceinline__ void cpa_commit() {
    asm volatile("cp.async.commit_group;" ::: "memory");
}
template<int N> __device__ __forceinline__ void cpa_wait() {
    asm volatile("cp.async.wait_group %0;" :: "n"(N) : "memory");
}

// ---------------- cvt kernel: fp32 -> fp16, 8 elems/thread ----------------
__global__ void cvt_f16_kernel(const float* __restrict__ src,
                               __half* __restrict__ dst, int n8) {
    int i = blockIdx.x * blockDim.x + threadIdx.x;
    if (i >= n8) return;
    float4 v0 = ((const float4*)src)[2*i];
    float4 v1 = ((const float4*)src)[2*i + 1];
    __half2 h0 = __floats2half2_rn(v0.x, v0.y);
    __half2 h1 = __floats2half2_rn(v0.z, v0.w);
    __half2 h2 = __floats2half2_rn(v1.x, v1.y);
    __half2 h3 = __floats2half2_rn(v1.z, v1.w);
    ((uint4*)dst)[i] = make_uint4(*(u32*)&h0, *(u32*)&h1, *(u32*)&h2, *(u32*)&h3);
}

// ---------------- kernel 0: RoPE tables ----------------
__global__ void rope_table_kernel() {
    int idx = blockIdx.x * blockDim.x + threadIdx.x;
    if (idx >= T_SZ * HALF) return;
    int t = idx / HALF;
    int j = idx % HALF;
    double inv = pow(10000.0, -(double)j / (double)HALF);
    double ang = (double)t * inv;
    g_cos[idx] = (float)cos(ang);
    g_sin[idx] = (float)sin(ang);
}

// ---------------- 128x128 fp16 GEMM, 256 thr, KS=16, 4-stage ----------------
// 8 warps in 2x4 grid; warp tile 64x32 (mi 4 x ni 4 m16n8 frags).
template<int LDB>
__device__ __forceinline__ void tc_gemm_f16(
    const __half* __restrict__ Ag, const __half* __restrict__ Bg,
    float (&acc)[4][4][4])
{
    extern __shared__ char sm[];
    const u32 smb = (u32)__cvta_generic_to_shared(sm);
    const int tid  = threadIdx.x;
    const int lane = tid & 31;
    const int warp = tid >> 5;            // 0..7
    const int wm = warp >> 2;             // 0..1
    const int wn = warp & 3;              // 0..3
    const int arow = (lane & 7) + ((lane >> 3) & 1) * 8;   // 0..15
    const int akk  = ((lane >> 4) & 1) * 8;                // 0 or 8 elems

    const int ar = tid >> 1;              // A row 0..127
    const int ac = (tid & 1) * 8;         // A elem chunk (8 elems = 16B)
    const int br = tid >> 4;              // B k-row 0..15
    const int bc = (tid & 15) * 8;        // B col chunk

#pragma unroll
    for (int mi = 0; mi < 4; mi++)
#pragma unroll
        for (int ni = 0; ni < 4; ni++)
#pragma unroll
            for (int r = 0; r < 4; r++)
                acc[mi][ni][r] = 0.f;

    const u32 a_soff = (u32)(ar * 48 + ac * 2);
    const u32 b_soff = (u32)(br * 272 + bc * 2);

#define ISSUE_STAGE(kt, st) do {                                                   \
        const u32 sb = smb + (u32)(st) * STG_BYTES;                                \
        cpa16(sb + A_OFF + a_soff, Ag + (size_t)ar * DM + (kt) * KS + ac);         \
        cpa16(sb + B_OFF + b_soff, Bg + (size_t)((kt) * KS + br) * LDB + bc);      \
        cpa_commit();                                                              \
    } while (0)

    ISSUE_STAGE(0, 0);
    ISSUE_STAGE(1, 1);
    ISSUE_STAGE(2, 2);

    const int KT = DM / KS;               // 64
    for (int kt = 0; kt < KT; kt++) {
        if (kt < KT - 2)       cpa_wait<2>();
        else if (kt == KT - 2) cpa_wait<1>();
        else                   cpa_wait<0>();
        __syncthreads();
        if (kt + 3 < KT) ISSUE_STAGE(kt + 3, (kt + 3) & 3);

        const u32 sb = smb + (u32)(kt & 3) * STG_BYTES;
        const u32 abase = sb + A_OFF + (u32)((wm*64 + arow) * 48 + akk * 2);
        const u32 bbase = sb + B_OFF + (u32)(arow * 272 + (wn*32 + akk) * 2);

        u32 A[4][4];
        u32 B[4][2];
#pragma unroll
        for (int mi = 0; mi < 4; mi++)
            ldsm4(A[mi][0], A[mi][1], A[mi][2], A[mi][3], abase + (u32)(mi * 16 * 48));
#pragma unroll
        for (int nj = 0; nj < 2; nj++) {
            u32 t0, t1, t2, t3;
            ldsm4t(t0, t1, t2, t3, bbase + (u32)(nj * 32));
            B[nj*2][0] = t0;
            B[nj*2][1] = t1;
            B[nj*2+1][0] = t2;
            B[nj*2+1][1] = t3;
        }
#pragma unroll
        for (int mi = 0; mi < 4; mi++)
#pragma unroll
            for (int ni = 0; ni < 4; ni++)
                mma_f16(acc[mi][ni], A[mi], B[ni]);
    }
#undef ISSUE_STAGE
}

// ---------------- kernel 1: QKV GEMM + RoPE epilogue ----------------
__global__ __launch_bounds__(256, 2) void qkv_tc_kernel() {
    const int row0 = blockIdx.y * 128;
    const int col0 = blockIdx.x * 128;
    float acc[4][4][4];
    tc_gemm_f16<3072>(g_xh + (size_t)row0 * DM, g_wqh + col0, acc);

    const int lane = threadIdx.x & 31;
    const int warp = threadIdx.x >> 5;
    const int wm = warp >> 2;
    const int wn = warp & 3;
    const int r0c = lane >> 2;
    const int cp  = (lane & 3) * 2;
    const int which = col0 >> 10;                      // 0=q 1=k 2=v
    float* dst = (which == 0) ? g_q : ((which == 1) ? g_k : g_v);
    const bool dorope = (which < 2);

#pragma unroll
    for (int mi = 0; mi < 4; mi++) {
#pragma unroll
        for (int half = 0; half < 2; half++) {
            const int gm = row0 + wm*64 + mi*16 + r0c + half*8;
            const int bb = gm >> 11;
            const int t  = gm & (T_SZ - 1);
#pragma unroll
            for (int ni = 0; ni < 4; ni++) {
                const int gn  = col0 + wn*32 + ni*8 + cp;
                const int rem = gn & 1023;
                const int h = rem >> 6;
                const int d = rem & 63;
                float v0 = acc[mi][ni][half*2 + 0];
                float v1 = acc[mi][ni][half*2 + 1];
                if (dorope) {
                    const int j = d >> 1;
                    const float c = g_cos[t*HALF + j];
                    const float s = g_sin[t*HALF + j];
                    const float re = v0*c - v1*s;
                    const float ro = v0*s + v1*c;
                    v0 = re;
                    v1 = ro;
                }
                *(float2*)&dst[((size_t)(bb*NH + h) * T_SZ + t) * DH + d] = make_float2(v0, v1);
            }
        }
    }
}

// ---------------- kernel 3: out projection + bias ----------------
__global__ __launch_bounds__(256, 2) void out_tc_kernel(const float* __restrict__ bias,
                                                        float* __restrict__ out) {
    const int row0 = blockIdx.y * 128;
    const int col0 = blockIdx.x * 128;
    float acc[4][4][4];
    tc_gemm_f16<1024>(g_ah + (size_t)row0 * DM, g_woh + col0, acc);

    const int lane = threadIdx.x & 31;
    const int warp = threadIdx.x >> 5;
    const int wm = warp >> 2;
    const int wn = warp & 3;
    const int r0c = lane >> 2;
    const int cp  = (lane & 3) * 2;

#pragma unroll
    for (int mi = 0; mi < 4; mi++) {
#pragma unroll
        for (int half = 0; half < 2; half++) {
            const int gm = row0 + wm*64 + mi*16 + r0c + half*8;
#pragma unroll
            for (int ni = 0; ni < 4; ni++) {
                const int gn = col0 + wn*32 + ni*8 + cp;
                const float b0 = bias[gn];
                const float b1 = bias[gn + 1];
                *(float2*)&out[(size_t)gm * DM + gn] =
                    make_float2(acc[mi][ni][half*2 + 0] + b0,
                                acc[mi][ni][half*2 + 1] + b1);
            }
        }
    }
}

// ---------------- shared attention tile body (pointer form) ----------------
__device__ __forceinline__ void attn_tile_body(
    float (*Qs)[64], float (*KP)[64], float (*Vs)[64],
    int tx, int ty, int qt, int kt, int jmax, bool global_tile,
    float (&m)[4], float (&l)[4], float (&acc)[4][4])
{
    float s[4][4];
#pragma unroll
    for (int i = 0; i < 4; i++)
#pragma unroll
        for (int j = 0; j < 4; j++) s[i][j] = 0.f;
#pragma unroll 16
    for (int d = 0; d < 64; d++) {
        float4 a = *(float4*)&Qs[d][ty*4];
        float4 b = *(float4*)&KP[d][tx*4];
        float ar[4] = {a.x, a.y, a.z, a.w};
        float br[4] = {b.x, b.y, b.z, b.w};
#pragma unroll
        for (int i = 0; i < 4; i++)
#pragma unroll
            for (int j = 0; j < 4; j++)
                s[i][j] = fmaf(ar[i], br[j], s[i][j]);
    }

    if (global_tile) {
#pragma unroll
        for (int i = 0; i < 4; i++)
#pragma unroll
            for (int j = 0; j < 4; j++) {
                const bool ok = (tx*4 + j) <= jmax;
                s[i][j] = ok ? s[i][j] * 0.125f : -1.0e9f;
            }
    } else {
        const int qb = qt * 64 + ty * 4;
        const int kb = kt * 64 + tx * 4;
#pragma unroll
        for (int i = 0; i < 4; i++) {
            const int q = qb + i;
            const bool qg = ((q & 63) == 0);
#pragma unroll
            for (int j = 0; j < 4; j++) {
                const int k = kb + j;
                const bool ok = (k <= q) && ((q - k) <= 127 || ((k & 63) == 0) || qg);
                s[i][j] = ok ? s[i][j] * 0.125f : -1.0e9f;
            }
        }
    }

    float rm[4];
#pragma unroll
    for (int i = 0; i < 4; i++)
        rm[i] = fmaxf(fmaxf(s[i][0], s[i][1]), fmaxf(s[i][2], s[i][3]));
#pragma unroll
    for (int off = 8; off > 0; off >>= 1)
#pragma unroll
        for (int i = 0; i < 4; i++)
            rm[i] = fmaxf(rm[i], __shfl_xor_sync(0xffffffffu, rm[i], off));

    float sc[4];
#pragma unroll
    for (int i = 0; i < 4; i++) {
        const float mn = fmaxf(m[i], rm[i]);
        sc[i] = __expf(m[i] - mn);
        m[i] = mn;
    }
    float rs[4];
#pragma unroll
    for (int i = 0; i < 4; i++) {
        float r = 0.f;
#pragma unroll
        for (int j = 0; j < 4; j++) {
            const float p = __expf(s[i][j] - m[i]);
            s[i][j] = p;
            r += p;
        }
        rs[i] = r;
    }
#pragma unroll
    for (int off = 8; off > 0; off >>= 1)
#pragma unroll
        for (int i = 0; i < 4; i++)
            rs[i] += __shfl_xor_sync(0xffffffffu, rs[i], off);
#pragma unroll
    for (int i = 0; i < 4; i++) {
        l[i] = l[i] * sc[i] + rs[i];
#pragma unroll
        for (int j = 0; j < 4; j++) acc[i][j] *= sc[i];
    }

    __syncthreads();
#pragma unroll
    for (int i = 0; i < 4; i++)
        *(float4*)&KP[ty*4 + i][tx*4] = make_float4(s[i][0], s[i][1], s[i][2], s[i][3]);
    __syncthreads();

#pragma unroll 8
    for (int kk = 0; kk < 64; kk += 4) {
        float4 a0 = *(float4*)&KP[ty*4 + 0][kk];
        float4 a1 = *(float4*)&KP[ty*4 + 1][kk];
        float4 a2 = *(float4*)&KP[ty*4 + 2][kk];
        float4 a3 = *(float4*)&KP[ty*4 + 3][kk];
        float ar[4][4] = {{a0.x,a0.y,a0.z,a0.w},{a1.x,a1.y,a1.z,a1.w},
                          {a2.x,a2.y,a2.z,a2.w},{a3.x,a3.y,a3.z,a3.w}};
#pragma unroll
        for (int u = 0; u < 4; u++) {
            float4 b = *(float4*)&Vs[kk + u][tx*4];
            float br[4] = {b.x, b.y, b.z, b.w};
#pragma unroll
            for (int i = 0; i < 4; i++)
#pragma unroll
                for (int j = 0; j < 4; j++)
                    acc[i][j] = fmaf(ar[i][u], br[j], acc[i][j]);
        }
    }
}

// ---------------- fused attention: main sparse flash + global-query partials ----
__global__ __launch_bounds__(256) void attn_fused_kernel() {
    extern __shared__ float smf[];
    const int bid = blockIdx.x;
    const int tid = threadIdx.x;
    const int tx = tid & 15, ty = tid >> 4;

    if (bid < 2048) {
        float (*Qs)[64] = (float(*)[64])smf;
        float (*KP)[64] = (float(*)[64])(smf + 64*64);
        float (*Vs)[64] = (float(*)[64])(smf + 2*64*64);
        const int qt = bid & 31;
        const int bh = bid >> 5;
        const float* qptr = g_q + (bh * T_SZ + qt * 64) * DH;
        const float* kptr = g_k + bh * T_SZ * DH;
        const float* vptr = g_v + bh * T_SZ * DH;

        {
            const int row = tid >> 2;
            const int cc  = tid & 3;
#pragma unroll
            for (int u = 0; u < 4; u++) {
                const int d0 = (cc + 4 * u) * 4;
                float4 qv = *(const float4*)&qptr[row * DH + d0];
                Qs[d0+0][row] = qv.x; Qs[d0+1][row] = qv.y;
                Qs[d0+2][row] = qv.z; Qs[d0+3][row] = qv.w;
            }
        }

        float m[4], l[4], acc[4][4];
#pragma unroll
        for (int i = 0; i < 4; i++) {
            m[i] = -1e30f; l[i] = 0.f;
#pragma unroll
            for (int j = 0; j < 4; j++) acc[i][j] = 0.f;
        }

        if (qt >= 3) {
            const int jmax = qt - 3;
            const int row = tid >> 2;
            const int cc  = tid & 3;
            const bool valid = (row <= jmax);
#pragma unroll
            for (int u = 0; u < 4; u++) {
                const int d0 = (cc + 4 * u) * 4;
                if (valid) {
                    float4 kv = *(const float4*)&kptr[(row << 6) * DH + d0];
                    KP[d0+0][row] = kv.x; KP[d0+1][row] = kv.y;
                    KP[d0+2][row] = kv.z; KP[d0+3][row] = kv.w;
                    *(float4*)&Vs[row][d0] = *(const float4*)&vptr[(row << 6) * DH + d0];
                } else {
                    KP[d0+0][row] = 0.f; KP[d0+1][row] = 0.f;
                    KP[d0+2][row] = 0.f; KP[d0+3][row] = 0.f;
                    *(float4*)&Vs[row][d0] = make_float4(0.f, 0.f, 0.f, 0.f);
                }
            }
            __syncthreads();
            attn_tile_body(Qs, KP, Vs, tx, ty, qt, 0, jmax, true, m, l, acc);
        }

        const int kt0 = (qt >= 2) ? (qt - 2) : 0;
        for (int kt = kt0; kt <= qt; kt++) {
            __syncthreads();
            {
                const int row = tid >> 2;
                const int cc  = tid & 3;
#pragma unroll
                for (int u = 0; u < 4; u++) {
                    const int d0 = (cc + 4 * u) * 4;
                    float4 kv = *(const float4*)&kptr[(kt * 64 + row) * DH + d0];
                    KP[d0+0][row] = kv.x; KP[d0+1][row] = kv.y;
                    KP[d0+2][row] = kv.z; KP[d0+3][row] = kv.w;
                    *(float4*)&Vs[row][d0] = *(const float4*)&vptr[(kt * 64 + row) * DH + d0];
                }
            }
            __syncthreads();
            attn_tile_body(Qs, KP, Vs, tx, ty, qt, kt, 0, false, m, l, acc);
        }

        const int bb = bh >> 4, hh = bh & 15;
#pragma unroll
        for (int i = 0; i < 4; i++) {
            const int q = qt * 64 + ty * 4 + i;
            const float inv = 1.0f / l[i];
            const int idx = (bb * T_SZ + q) * DM + hh * DH + tx * 4;
            *(float4*)&g_attn[idx] = make_float4(acc[i][0]*inv, acc[i][1]*inv,
                                                 acc[i][2]*inv, acc[i][3]*inv);
        }
        return;
    }

    // ---- global-query split-K partials ----
    {
        float (*Qs2)[32] = (float(*)[32])smf;
        float (*KP)[64]  = (float(*)[64])(smf + 64*32);
        float (*Vs)[64]  = (float(*)[64])(smf + 64*32 + 64*64);
        const int id = bid - 2048;
        const int bh = id >> 2;
        const int kc = id & 3;
        const float* qbase = g_q + bh * T_SZ * DH;
        const float* kbase = g_k + bh * T_SZ * DH;
        const float* vbase = g_v + bh * T_SZ * DH;

        {
            const int r  = tid >> 3;
            const int d0 = (tid & 7) * 8;
            float4 q0 = *(const float4*)&qbase[(r << 6) * DH + d0];
            float4 q1 = *(const float4*)&qbase[(r << 6) * DH + d0 + 4];
            Qs2[d0+0][r] = q0.x; Qs2[d0+1][r] = q0.y; Qs2[d0+2][r] = q0.z; Qs2[d0+3][r] = q0.w;
            Qs2[d0+4][r] = q1.x; Qs2[d0+5][r] = q1.y; Qs2[d0+6][r] = q1.z; Qs2[d0+7][r] = q1.w;
        }

        float m[2] = {-1e30f, -1e30f}, l[2] = {0.f, 0.f};
        float acc[2][4];
#pragma unroll
        for (int i = 0; i < 2; i++)
#pragma unroll
            for (int j = 0; j < 4; j++) acc[i][j] = 0.f;

        for (int it = 0; it < 8; it++) {
            const int kt = kc * 8 + it;
            __syncthreads();
            {
                const int row = tid >> 2;
                const int cc  = tid & 3;
#pragma unroll
                for (int u = 0; u < 4; u++) {
                    const int d0 = (cc + 4 * u) * 4;
                    float4 kv = *(const float4*)&kbase[(kt * 64 + row) * DH + d0];
                    KP[d0+0][row] = kv.x; KP[d0+1][row] = kv.y;
                    KP[d0+2][row] = kv.z; KP[d0+3][row] = kv.w;
                    *(float4*)&Vs[row][d0] = *(const float4*)&vbase[(kt * 64 + row) * DH + d0];
                }
            }
            __syncthreads();

            float s[2][4];
#pragma unroll
            for (int i = 0; i < 2; i++)
#pragma unroll
                for (int j = 0; j < 4; j++) s[i][j] = 0.f;
#pragma unroll 16
            for (int d = 0; d < 64; d++) {
                const float a0 = Qs2[d][ty*2];
                const float a1 = Qs2[d][ty*2 + 1];
                float4 b = *(float4*)&KP[d][tx*4];
                float br[4] = {b.x, b.y, b.z, b.w};
#pragma unroll
                for (int j = 0; j < 4; j++) {
                    s[0][j] = fmaf(a0, br[j], s[0][j]);
                    s[1][j] = fmaf(a1, br[j], s[1][j]);
                }
            }
#pragma unroll
            for (int i = 0; i < 2; i++) {
                const int qv = (ty*2 + i) << 6;
#pragma unroll
                for (int j = 0; j < 4; j++) {
                    const int k = kt * 64 + tx*4 + j;
                    s[i][j] = (k <= qv) ? s[i][j] * 0.125f : -1.0e9f;
                }
            }

            float rm[2];
#pragma unroll
            for (int i = 0; i < 2; i++)
                rm[i] = fmaxf(fmaxf(s[i][0], s[i][1]), fmaxf(s[i][2], s[i][3]));
#pragma unroll
            for (int off = 8; off > 0; off >>= 1)
#pragma unroll
                for (int i = 0; i < 2; i++)
                    rm[i] = fmaxf(rm[i], __shfl_xor_sync(0xffffffffu, rm[i], off));

            float sc[2], rs[2];
#pragma unroll
            for (int i = 0; i < 2; i++) {
                const float mn = fmaxf(m[i], rm[i]);
                sc[i] = __expf(m[i] - mn);
                m[i] = mn;
                float r = 0.f;
#pragma unroll
                for (int j = 0; j < 4; j++) {
                    const float p = __expf(s[i][j] - m[i]);
                    s[i][j] = p;
                    r += p;
                }
                rs[i] = r;
            }
#pragma unroll
            for (int off = 8; off > 0; off >>= 1)
#pragma unroll
                for (int i = 0; i < 2; i++)
                    rs[i] += __shfl_xor_sync(0xffffffffu, rs[i], off);
#pragma unroll
            for (int i = 0; i < 2; i++) {
                l[i] = l[i] * sc[i] + rs[i];
#pragma unroll
                for (int j = 0; j < 4; j++) acc[i][j] *= sc[i];
            }

            __syncthreads();
#pragma unroll
            for (int i = 0; i < 2; i++)
                *(float4*)&KP[ty*2 + i][tx*4] = make_float4(s[i][0], s[i][1], s[i][2], s[i][3]);
            __syncthreads();

#pragma unroll 8
            for (int kk = 0; kk < 64; kk += 4) {
                float4 a0 = *(float4*)&KP[ty*2 + 0][kk];
                float4 a1 = *(float4*)&KP[ty*2 + 1][kk];
                float ar[2][4] = {{a0.x,a0.y,a0.z,a0.w},{a1.x,a1.y,a1.z,a1.w}};
#pragma unroll
                for (int u = 0; u < 4; u++) {
                    float4 b = *(float4*)&Vs[kk + u][tx*4];
                    float br[4] = {b.x, b.y, b.z, b.w};
#pragma unroll
                    for (int i = 0; i < 2; i++)
#pragma unroll
                        for (int j = 0; j < 4; j++)
                            acc[i][j] = fmaf(ar[i][u], br[j], acc[i][j]);
                }
            }
        }

        const int base = (bh * 4 + kc) * 32;
#pragma unroll
        for (int i = 0; i < 2; i++) {
            const int r = ty*2 + i;
            *(float4*)&g_pacc[(base + r) * 64 + tx*4] =
                make_float4(acc[i][0], acc[i][1], acc[i][2], acc[i][3]);
            if (tx == 0) { g_pm[base + r] = m[i]; g_pl[base + r] = l[i]; }
        }
    }
}

// ---------------- merge split-K partials ----------------
__global__ __launch_bounds__(256) void attn_gq_combine() {
    const int bh = blockIdx.x;
    const int b = bh >> 4, h = bh & 15;
    for (int idx = threadIdx.x; idx < 32 * 64; idx += 256) {
        const int r = idx >> 6, d = idx & 63;
        float M = -1e30f;
#pragma unroll
        for (int kc = 0; kc < 4; kc++)
            M = fmaxf(M, g_pm[(bh*4 + kc)*32 + r]);
        float l = 0.f, o = 0.f;
#pragma unroll
        for (int kc = 0; kc < 4; kc++) {
            const int p = (bh*4 + kc)*32 + r;
            const float w = __expf(g_pm[p] - M);
            l += w * g_pl[p];
            o += w * g_pacc[p * 64 + d];
        }
        g_attn[(b * T_SZ + (r << 6)) * DM + h * DH + d] = o / l;
    }
}

// ---------------- launch ----------------
extern "C" void kernel_launch(void* const* d_in, const int* in_sizes, int n_in,
                              void* d_out, int out_size) {
    const float *x = 0;
    const float *Wqkv = 0;
    const float *Wout = 0;
    const float *bout = 0;
    for (int i = 0; i < n_in; i++) {
        switch (in_sizes[i]) {
            case B_SZ*T_SZ*DM: x    = (const float*)d_in[i]; break;
            case DM*3*DM:      Wqkv = (const float*)d_in[i]; break;
            case DM*DM:        Wout = (const float*)d_in[i]; break;
            case DM:           bout = (const float*)d_in[i]; break;
        }
    }
    float* out = (float*)d_out;

    cudaFuncSetAttribute(qkv_tc_kernel, cudaFuncAttributeMaxDynamicSharedMemorySize, GEMM_SMEM);
    cudaFuncSetAttribute(out_tc_kernel, cudaFuncAttributeMaxDynamicSharedMemorySize, GEMM_SMEM);

    __half *xh, *wqh, *woh, *ah;
    float* attn_f;
    cudaGetSymbolAddress((void**)&xh,  g_xh);
    cudaGetSymbolAddress((void**)&wqh, g_wqh);
    cudaGetSymbolAddress((void**)&woh, g_woh);
    cudaGetSymbolAddress((void**)&ah,  g_ah);
    cudaGetSymbolAddress((void**)&attn_f, g_attn);

    rope_table_kernel<<<(T_SZ*HALF + 255) / 256, 256>>>();
    cvt_f16_kernel<<<(B_SZ*T_SZ*DM/8 + 255) / 256, 256>>>(x, xh, B_SZ*T_SZ*DM/8);
    cvt_f16_kernel<<<(DM*3*DM/8 + 255) / 256, 256>>>(Wqkv, wqh, DM*3*DM/8);
    cvt_f16_kernel<<<(DM*DM/8 + 255) / 256, 256>>>(Wout, woh, DM*DM/8);

    qkv_tc_kernel<<<dim3(3*DM/128, B_SZ*T_SZ/128), 256, GEMM_SMEM>>>();
    attn_fused_kernel<<<2048 + 256, 256, 48*1024>>>();
    attn_gq_combine<<<B_SZ*NH, 256>>>();
    cvt_f16_kernel<<<(B_SZ*T_SZ*DM/8 + 255) / 256, 256>>>(attn_f, ah, B_SZ*T_SZ*DM/8);
    out_tc_kernel<<<dim3(DM/128, B_SZ*T_SZ/128), 256, GEMM_SMEM>>>(bout, out);
}

// round 14
// speedup vs baseline: 2.1615x; 1.2354x over previous
#include <cuda_runtime.h>
#include <cuda_fp16.h>
#include <math.h>

#define B_SZ 4
#define T_SZ 2048
#define DM   1024
#define NH   16
#define DH   64
#define HALF 32   // DH/2

typedef unsigned int u32;

// ---------------- scratch (device globals; no runtime allocation) ----------------
__device__ float g_q[B_SZ*NH*T_SZ*DH];
__device__ float g_k[B_SZ*NH*T_SZ*DH];
__device__ float g_v[B_SZ*NH*T_SZ*DH];
__device__ float g_attn[B_SZ*T_SZ*DM];
__device__ float g_cos[T_SZ*HALF];
__device__ float g_sin[T_SZ*HALF];
__device__ float g_pm[64*4*32];
__device__ float g_pl[64*4*32];
__device__ float g_pacc[64*4*32*64];
// pre-converted fp16 operands
__device__ __half g_xh[B_SZ*T_SZ*DM];
__device__ __half g_wqh[DM*3*DM];
__device__ __half g_woh[DM*DM];
__device__ __half g_ah[B_SZ*T_SZ*DM];
// fp16 q/k/v for tensor-core attention
__device__ __half g_qf16[B_SZ*NH*T_SZ*DH];
__device__ __half g_kf16[B_SZ*NH*T_SZ*DH];
__device__ __half g_vf16[B_SZ*NH*T_SZ*DH];

// ---------------- GEMM tiling constants ----------------
#define KS        16
#define NSTG      4
#define A_OFF     0
#define B_OFF     6144
#define STG_BYTES 10496
#define GEMM_SMEM (NSTG * STG_BYTES)   // 41984

// attention smem (halfs): Q[128][72] | K[64][72] | V[64][72]
#define AQ_OFF 0
#define AK_OFF 9216
#define AV_OFF 13824
#define ATTN_SMEM 49152

// ---------------- tensor-core / async helpers ----------------
__device__ __forceinline__ void ldsm4(u32& r0, u32& r1, u32& r2, u32& r3, u32 a) {
    asm volatile("ldmatrix.sync.aligned.m8n8.x4.shared.b16 {%0,%1,%2,%3}, [%4];"
                 : "=r"(r0), "=r"(r1), "=r"(r2), "=r"(r3) : "r"(a));
}
__device__ __forceinline__ void ldsm4t(u32& r0, u32& r1, u32& r2, u32& r3, u32 a) {
    asm volatile("ldmatrix.sync.aligned.m8n8.x4.trans.shared.b16 {%0,%1,%2,%3}, [%4];"
                 : "=r"(r0), "=r"(r1), "=r"(r2), "=r"(r3) : "r"(a));
}
__device__ __forceinline__ void mma_f16(float* d, const u32* a, const u32* b) {
    asm volatile("mma.sync.aligned.m16n8k16.row.col.f32.f16.f16.f32 "
                 "{%0,%1,%2,%3}, {%4,%5,%6,%7}, {%8,%9}, {%0,%1,%2,%3};"
                 : "+f"(d[0]), "+f"(d[1]), "+f"(d[2]), "+f"(d[3])
                 : "r"(a[0]), "r"(a[1]), "r"(a[2]), "r"(a[3]), "r"(b[0]), "r"(b[1]));
}
__device__ __forceinline__ void cpa16(u32 dst, const void* src) {
    asm volatile("cp.async.cg.shared.global [%0], [%1], 16;" :: "r"(dst), "l"(src) : "memory");
}
__device__ __forceinline__ void cpa_commit() {
    asm volatile("cp.async.commit_group;" ::: "memory");
}
template<int N> __device__ __forceinline__ void cpa_wait() {
    asm volatile("cp.async.wait_group %0;" :: "n"(N) : "memory");
}

// ---------------- cvt kernel: fp32 -> fp16, 8 elems/thread ----------------
__global__ void cvt_f16_kernel(const float* __restrict__ src,
                               __half* __restrict__ dst, int n8) {
    int i = blockIdx.x * blockDim.x + threadIdx.x;
    if (i >= n8) return;
    float4 v0 = ((const float4*)src)[2*i];
    float4 v1 = ((const float4*)src)[2*i + 1];
    __half2 h0 = __floats2half2_rn(v0.x, v0.y);
    __half2 h1 = __floats2half2_rn(v0.z, v0.w);
    __half2 h2 = __floats2half2_rn(v1.x, v1.y);
    __half2 h3 = __floats2half2_rn(v1.z, v1.w);
    ((uint4*)dst)[i] = make_uint4(*(u32*)&h0, *(u32*)&h1, *(u32*)&h2, *(u32*)&h3);
}

// ---------------- kernel 0: RoPE tables ----------------
__global__ void rope_table_kernel() {
    int idx = blockIdx.x * blockDim.x + threadIdx.x;
    if (idx >= T_SZ * HALF) return;
    int t = idx / HALF;
    int j = idx % HALF;
    double inv = pow(10000.0, -(double)j / (double)HALF);
    double ang = (double)t * inv;
    g_cos[idx] = (float)cos(ang);
    g_sin[idx] = (float)sin(ang);
}

// ---------------- 128x128 fp16 GEMM, 256 thr, KS=16, 4-stage ----------------
template<int LDB>
__device__ __forceinline__ void tc_gemm_f16(
    const __half* __restrict__ Ag, const __half* __restrict__ Bg,
    float (&acc)[4][4][4])
{
    extern __shared__ char sm[];
    const u32 smb = (u32)__cvta_generic_to_shared(sm);
    const int tid  = threadIdx.x;
    const int lane = tid & 31;
    const int warp = tid >> 5;
    const int wm = warp >> 2;
    const int wn = warp & 3;
    const int arow = (lane & 7) + ((lane >> 3) & 1) * 8;
    const int akk  = ((lane >> 4) & 1) * 8;

    const int ar = tid >> 1;
    const int ac = (tid & 1) * 8;
    const int br = tid >> 4;
    const int bc = (tid & 15) * 8;

#pragma unroll
    for (int mi = 0; mi < 4; mi++)
#pragma unroll
        for (int ni = 0; ni < 4; ni++)
#pragma unroll
            for (int r = 0; r < 4; r++)
                acc[mi][ni][r] = 0.f;

    const u32 a_soff = (u32)(ar * 48 + ac * 2);
    const u32 b_soff = (u32)(br * 272 + bc * 2);

#define ISSUE_STAGE(kt, st) do {                                                   \
        const u32 sb = smb + (u32)(st) * STG_BYTES;                                \
        cpa16(sb + A_OFF + a_soff, Ag + (size_t)ar * DM + (kt) * KS + ac);         \
        cpa16(sb + B_OFF + b_soff, Bg + (size_t)((kt) * KS + br) * LDB + bc);      \
        cpa_commit();                                                              \
    } while (0)

    ISSUE_STAGE(0, 0);
    ISSUE_STAGE(1, 1);
    ISSUE_STAGE(2, 2);

    const int KT = DM / KS;
    for (int kt = 0; kt < KT; kt++) {
        if (kt < KT - 2)       cpa_wait<2>();
        else if (kt == KT - 2) cpa_wait<1>();
        else                   cpa_wait<0>();
        __syncthreads();
        if (kt + 3 < KT) ISSUE_STAGE(kt + 3, (kt + 3) & 3);

        const u32 sb = smb + (u32)(kt & 3) * STG_BYTES;
        const u32 abase = sb + A_OFF + (u32)((wm*64 + arow) * 48 + akk * 2);
        const u32 bbase = sb + B_OFF + (u32)(arow * 272 + (wn*32 + akk) * 2);

        u32 A[4][4];
        u32 B[4][2];
#pragma unroll
        for (int mi = 0; mi < 4; mi++)
            ldsm4(A[mi][0], A[mi][1], A[mi][2], A[mi][3], abase + (u32)(mi * 16 * 48));
#pragma unroll
        for (int nj = 0; nj < 2; nj++) {
            u32 t0, t1, t2, t3;
            ldsm4t(t0, t1, t2, t3, bbase + (u32)(nj * 32));
            B[nj*2][0] = t0;
            B[nj*2][1] = t1;
            B[nj*2+1][0] = t2;
            B[nj*2+1][1] = t3;
        }
#pragma unroll
        for (int mi = 0; mi < 4; mi++)
#pragma unroll
            for (int ni = 0; ni < 4; ni++)
                mma_f16(acc[mi][ni], A[mi], B[ni]);
    }
#undef ISSUE_STAGE
}

// ---------------- kernel 1: QKV GEMM + RoPE epilogue (fp32 + fp16 outputs) ------
__global__ __launch_bounds__(256, 2) void qkv_tc_kernel() {
    const int row0 = blockIdx.y * 128;
    const int col0 = blockIdx.x * 128;
    float acc[4][4][4];
    tc_gemm_f16<3072>(g_xh + (size_t)row0 * DM, g_wqh + col0, acc);

    const int lane = threadIdx.x & 31;
    const int warp = threadIdx.x >> 5;
    const int wm = warp >> 2;
    const int wn = warp & 3;
    const int r0c = lane >> 2;
    const int cp  = (lane & 3) * 2;
    const int which = col0 >> 10;
    float* dst = (which == 0) ? g_q : ((which == 1) ? g_k : g_v);
    __half* dsth = (which == 0) ? g_qf16 : ((which == 1) ? g_kf16 : g_vf16);
    const bool dorope = (which < 2);

#pragma unroll
    for (int mi = 0; mi < 4; mi++) {
#pragma unroll
        for (int half = 0; half < 2; half++) {
            const int gm = row0 + wm*64 + mi*16 + r0c + half*8;
            const int bb = gm >> 11;
            const int t  = gm & (T_SZ - 1);
#pragma unroll
            for (int ni = 0; ni < 4; ni++) {
                const int gn  = col0 + wn*32 + ni*8 + cp;
                const int rem = gn & 1023;
                const int h = rem >> 6;
                const int d = rem & 63;
                float v0 = acc[mi][ni][half*2 + 0];
                float v1 = acc[mi][ni][half*2 + 1];
                if (dorope) {
                    const int j = d >> 1;
                    const float c = g_cos[t*HALF + j];
                    const float s = g_sin[t*HALF + j];
                    const float re = v0*c - v1*s;
                    const float ro = v0*s + v1*c;
                    v0 = re;
                    v1 = ro;
                }
                const size_t idx = ((size_t)(bb*NH + h) * T_SZ + t) * DH + d;
                *(float2*)&dst[idx] = make_float2(v0, v1);
                __half2 hp = __floats2half2_rn(v0, v1);
                *(u32*)&dsth[idx] = *(u32*)&hp;
            }
        }
    }
}

// ---------------- kernel 3: out projection + bias ----------------
__global__ __launch_bounds__(256, 2) void out_tc_kernel(const float* __restrict__ bias,
                                                        float* __restrict__ out) {
    const int row0 = blockIdx.y * 128;
    const int col0 = blockIdx.x * 128;
    float acc[4][4][4];
    tc_gemm_f16<1024>(g_ah + (size_t)row0 * DM, g_woh + col0, acc);

    const int lane = threadIdx.x & 31;
    const int warp = threadIdx.x >> 5;
    const int wm = warp >> 2;
    const int wn = warp & 3;
    const int r0c = lane >> 2;
    const int cp  = (lane & 3) * 2;

#pragma unroll
    for (int mi = 0; mi < 4; mi++) {
#pragma unroll
        for (int half = 0; half < 2; half++) {
            const int gm = row0 + wm*64 + mi*16 + r0c + half*8;
#pragma unroll
            for (int ni = 0; ni < 4; ni++) {
                const int gn = col0 + wn*32 + ni*8 + cp;
                const float b0 = bias[gn];
                const float b1 = bias[gn + 1];
                *(float2*)&out[(size_t)gm * DM + gn] =
                    make_float2(acc[mi][ni][half*2 + 0] + b0,
                                acc[mi][ni][half*2 + 1] + b1);
            }
        }
    }
}

// ---------------- fused attention ----------------
// Blocks [0,1024): tensor-core sparse flash. Block p,bh handles q-rows p*128..+127
// as two 64-row subtiles (warps 0-3 / 4-7). K/V smem loads shared.
// Blocks [1024,1280): fp32 global-query split-K partials (unchanged).
__global__ __launch_bounds__(256) void attn_fused_kernel() {
    extern __shared__ float smf[];
    const int bid = blockIdx.x;
    const int tid = threadIdx.x;

    if (bid < 1024) {
        __half* smh = (__half*)smf;
        const u32 smb = (u32)__cvta_generic_to_shared(smh);
        const int p  = bid & 15;
        const int bh = bid >> 4;
        const int lane = tid & 31;
        const int warp = tid >> 5;
        const int group = warp >> 2;       // q-subtile 0/1
        const int mb    = warp & 3;        // 16-row block within subtile
        const int qt    = 2*p + group;     // 64-granular q-tile id
        const int arow  = (lane & 7) + ((lane >> 3) & 1) * 8;
        const int akk8  = ((lane >> 4) & 1) * 8;

        const __half* qhp = g_qf16 + (size_t)(bh * T_SZ + p * 128) * DH;
        const __half* khp = g_kf16 + (size_t)bh * T_SZ * DH;
        const __half* vhp = g_vf16 + (size_t)bh * T_SZ * DH;

        // stage Q (128 rows x 64 halfs) into smem [128][72]
        for (int i = 0; i < 4; i++) {
            const int idx = tid + i * 256;           // 0..1023
            const int row = idx >> 3;
            const int ch  = idx & 7;
            *(uint4*)&smh[AQ_OFF + row * 72 + ch * 8] =
                *(const uint4*)&qhp[row * 64 + ch * 8];
        }
        __syncthreads();

        // preload Q A-frags: rows group*64+mb*16 .. +15, k = d (4 chunks)
        u32 QA[4][4];
        {
            const u32 qb = smb + (u32)(2 * (AQ_OFF + (group*64 + mb*16 + arow) * 72));
#pragma unroll
            for (int kc = 0; kc < 4; kc++)
                ldsm4(QA[kc][0], QA[kc][1], QA[kc][2], QA[kc][3],
                      qb + (u32)(2 * (kc * 16 + akk8)));
        }

        float m[2] = {-1e30f, -1e30f};
        float l[2] = {0.f, 0.f};
        float O[8][4];
#pragma unroll
        for (int nf = 0; nf < 8; nf++)
#pragma unroll
            for (int e = 0; e < 4; e++) O[nf][e] = 0.f;

        const int jmax_w = qt - 3;                 // per-warp global-key limit
        const int jmax_pair = 2*p - 2;             // gather rows needed
        const int ktlo = (2*p >= 2) ? (2*p - 2) : 0;
        const int n_iter = (2*p + 1) - ktlo + 1 + (p >= 1 ? 1 : 0);

        for (int it = 0; it < n_iter; it++) {
            const bool global_tile = (p >= 1) && (it == 0);
            const int kt = global_tile ? -1 : (ktlo + it - (p >= 1 ? 1 : 0));
            __syncthreads();   // protect prior K/V reads (and Q frag reads, it=0)
            // load K/V tile (1024 uint4 across 4 iters)
            for (int i = 0; i < 4; i++) {
                const int idx = tid + i * 256;
                const bool isV = idx >= 512;
                const int ri = (idx & 511) >> 3;
                const int ch = idx & 7;
                const int off = (isV ? AV_OFF : AK_OFF) + ri * 72 + ch * 8;
                const __half* src = isV ? vhp : khp;
                if (global_tile) {
                    if (ri <= jmax_pair)
                        *(uint4*)&smh[off] = *(const uint4*)&src[(ri << 6) * 64 + ch * 8];
                    else
                        *(uint4*)&smh[off] = make_uint4(0, 0, 0, 0);
                } else {
                    *(uint4*)&smh[off] = *(const uint4*)&src[(kt * 64 + ri) * 64 + ch * 8];
                }
            }
            __syncthreads();

            const bool active = global_tile ? (jmax_w >= 0)
                                            : (kt >= qt - 2 && kt <= qt);
            if (!active) continue;

            // S = Q K^T (per warp: 16 rows x 64 cols)
            float C[8][4];
#pragma unroll
            for (int nf = 0; nf < 8; nf++)
#pragma unroll
                for (int e = 0; e < 4; e++) C[nf][e] = 0.f;
#pragma unroll
            for (int nb = 0; nb < 4; nb++) {
                const u32 kb = smb + (u32)(2 * (AK_OFF + (nb*16 + arow) * 72));
#pragma unroll
                for (int kc = 0; kc < 4; kc++) {
                    u32 t0, t1, t2, t3;
                    ldsm4(t0, t1, t2, t3, kb + (u32)(2 * (kc * 16 + akk8)));
                    u32 b0[2] = {t0, t2};
                    u32 b1[2] = {t1, t3};
                    mma_f16(C[2*nb],     QA[kc], b0);
                    mma_f16(C[2*nb + 1], QA[kc], b1);
                }
            }

            // mask + scale
            const int rbase = qt * 64 + mb * 16 + (lane >> 2);
            const int cbase = (lane & 3) * 2;
#pragma unroll
            for (int nf = 0; nf < 8; nf++) {
#pragma unroll
                for (int e = 0; e < 4; e++) {
                    const int q = rbase + (e >> 1) * 8;
                    const int col = nf * 8 + cbase + (e & 1);
                    bool ok;
                    if (global_tile) {
                        ok = (col <= jmax_w);
                    } else {
                        const int k = kt * 64 + col;
                        ok = (k <= q) && ((q - k) <= 127 || ((k & 63) == 0) || ((q & 63) == 0));
                    }
                    C[nf][e] = ok ? C[nf][e] * 0.125f : -1.0e9f;
                }
            }

            // row max (rows r, r+8) over 64 cols: local + quad shfl
            float rm[2] = {-1e30f, -1e30f};
#pragma unroll
            for (int nf = 0; nf < 8; nf++) {
                rm[0] = fmaxf(rm[0], fmaxf(C[nf][0], C[nf][1]));
                rm[1] = fmaxf(rm[1], fmaxf(C[nf][2], C[nf][3]));
            }
#pragma unroll
            for (int off = 1; off <= 2; off <<= 1) {
                rm[0] = fmaxf(rm[0], __shfl_xor_sync(0xffffffffu, rm[0], off));
                rm[1] = fmaxf(rm[1], __shfl_xor_sync(0xffffffffu, rm[1], off));
            }

            float sc[2];
#pragma unroll
            for (int i = 0; i < 2; i++) {
                const float mn = fmaxf(m[i], rm[i]);
                sc[i] = __expf(m[i] - mn);
                m[i] = mn;
            }
            float rs[2] = {0.f, 0.f};
#pragma unroll
            for (int nf = 0; nf < 8; nf++) {
                C[nf][0] = __expf(C[nf][0] - m[0]);
                C[nf][1] = __expf(C[nf][1] - m[0]);
                C[nf][2] = __expf(C[nf][2] - m[1]);
                C[nf][3] = __expf(C[nf][3] - m[1]);
                rs[0] += C[nf][0] + C[nf][1];
                rs[1] += C[nf][2] + C[nf][3];
            }
#pragma unroll
            for (int off = 1; off <= 2; off <<= 1) {
                rs[0] += __shfl_xor_sync(0xffffffffu, rs[0], off);
                rs[1] += __shfl_xor_sync(0xffffffffu, rs[1], off);
            }
#pragma unroll
            for (int i = 0; i < 2; i++) l[i] = l[i] * sc[i] + rs[i];
#pragma unroll
            for (int nf = 0; nf < 8; nf++) {
                O[nf][0] *= sc[0];
                O[nf][1] *= sc[0];
                O[nf][2] *= sc[1];
                O[nf][3] *= sc[1];
            }

            // pack P into A-frags (k-chunk j covers S cols 16j..16j+15)
            u32 PA[4][4];
#pragma unroll
            for (int j = 0; j < 4; j++) {
                __half2 h0 = __floats2half2_rn(C[2*j][0],   C[2*j][1]);
                __half2 h1 = __floats2half2_rn(C[2*j][2],   C[2*j][3]);
                __half2 h2 = __floats2half2_rn(C[2*j+1][0], C[2*j+1][1]);
                __half2 h3 = __floats2half2_rn(C[2*j+1][2], C[2*j+1][3]);
                PA[j][0] = *(u32*)&h0;
                PA[j][1] = *(u32*)&h1;
                PA[j][2] = *(u32*)&h2;
                PA[j][3] = *(u32*)&h3;
            }

            // O += P V  (V [kpos][d] via trans ldmatrix, same pattern as GEMM B)
#pragma unroll
            for (int kc = 0; kc < 4; kc++) {
                const u32 vb = smb + (u32)(2 * (AV_OFF + (kc*16 + arow) * 72));
#pragma unroll
                for (int db = 0; db < 4; db++) {
                    u32 t0, t1, t2, t3;
                    ldsm4t(t0, t1, t2, t3, vb + (u32)(2 * (db * 16 + akk8)));
                    u32 b0[2] = {t0, t1};
                    u32 b1[2] = {t2, t3};
                    mma_f16(O[2*db],     PA[kc], b0);
                    mma_f16(O[2*db + 1], PA[kc], b1);
                }
            }
        }

        // normalize + store fp32 g_attn
        const int bb = bh >> 4;
        const int hh = bh & 15;
        const float inv0 = 1.f / l[0];
        const float inv1 = 1.f / l[1];
        const int r0 = qt * 64 + mb * 16 + (lane >> 2);
        const int c0 = (lane & 3) * 2;
#pragma unroll
        for (int nf = 0; nf < 8; nf++) {
            const int d = nf * 8 + c0;
            *(float2*)&g_attn[((size_t)(bb * T_SZ + r0) * DM) + hh * 64 + d] =
                make_float2(O[nf][0] * inv0, O[nf][1] * inv0);
            *(float2*)&g_attn[((size_t)(bb * T_SZ + r0 + 8) * DM) + hh * 64 + d] =
                make_float2(O[nf][2] * inv1, O[nf][3] * inv1);
        }
        return;
    }

    // ---- global-query split-K partials (fp32, unchanged) ----
    {
        const int tx = tid & 15, ty = tid >> 4;
        float (*Qs2)[32] = (float(*)[32])smf;
        float (*KP)[64]  = (float(*)[64])(smf + 64*32);
        float (*Vs)[64]  = (float(*)[64])(smf + 64*32 + 64*64);
        const int id = bid - 1024;
        const int bh = id >> 2;
        const int kc = id & 3;
        const float* qbase = g_q + bh * T_SZ * DH;
        const float* kbase = g_k + bh * T_SZ * DH;
        const float* vbase = g_v + bh * T_SZ * DH;

        {
            const int r  = tid >> 3;
            const int d0 = (tid & 7) * 8;
            float4 q0 = *(const float4*)&qbase[(r << 6) * DH + d0];
            float4 q1 = *(const float4*)&qbase[(r << 6) * DH + d0 + 4];
            Qs2[d0+0][r] = q0.x; Qs2[d0+1][r] = q0.y; Qs2[d0+2][r] = q0.z; Qs2[d0+3][r] = q0.w;
            Qs2[d0+4][r] = q1.x; Qs2[d0+5][r] = q1.y; Qs2[d0+6][r] = q1.z; Qs2[d0+7][r] = q1.w;
        }

        float m[2] = {-1e30f, -1e30f}, l[2] = {0.f, 0.f};
        float acc[2][4];
#pragma unroll
        for (int i = 0; i < 2; i++)
#pragma unroll
            for (int j = 0; j < 4; j++) acc[i][j] = 0.f;

        for (int it = 0; it < 8; it++) {
            const int kt = kc * 8 + it;
            __syncthreads();
            {
                const int row = tid >> 2;
                const int cc  = tid & 3;
#pragma unroll
                for (int u = 0; u < 4; u++) {
                    const int d0 = (cc + 4 * u) * 4;
                    float4 kv = *(const float4*)&kbase[(kt * 64 + row) * DH + d0];
                    KP[d0+0][row] = kv.x; KP[d0+1][row] = kv.y;
                    KP[d0+2][row] = kv.z; KP[d0+3][row] = kv.w;
                    *(float4*)&Vs[row][d0] = *(const float4*)&vbase[(kt * 64 + row) * DH + d0];
                }
            }
            __syncthreads();

            float s[2][4];
#pragma unroll
            for (int i = 0; i < 2; i++)
#pragma unroll
                for (int j = 0; j < 4; j++) s[i][j] = 0.f;
#pragma unroll 16
            for (int d = 0; d < 64; d++) {
                const float a0 = Qs2[d][ty*2];
                const float a1 = Qs2[d][ty*2 + 1];
                float4 b = *(float4*)&KP[d][tx*4];
                float br[4] = {b.x, b.y, b.z, b.w};
#pragma unroll
                for (int j = 0; j < 4; j++) {
                    s[0][j] = fmaf(a0, br[j], s[0][j]);
                    s[1][j] = fmaf(a1, br[j], s[1][j]);
                }
            }
#pragma unroll
            for (int i = 0; i < 2; i++) {
                const int qv = (ty*2 + i) << 6;
#pragma unroll
                for (int j = 0; j < 4; j++) {
                    const int k = kt * 64 + tx*4 + j;
                    s[i][j] = (k <= qv) ? s[i][j] * 0.125f : -1.0e9f;
                }
            }

            float rm[2];
#pragma unroll
            for (int i = 0; i < 2; i++)
                rm[i] = fmaxf(fmaxf(s[i][0], s[i][1]), fmaxf(s[i][2], s[i][3]));
#pragma unroll
            for (int off = 8; off > 0; off >>= 1)
#pragma unroll
                for (int i = 0; i < 2; i++)
                    rm[i] = fmaxf(rm[i], __shfl_xor_sync(0xffffffffu, rm[i], off));

            float sc[2], rs[2];
#pragma unroll
            for (int i = 0; i < 2; i++) {
                const float mn = fmaxf(m[i], rm[i]);
                sc[i] = __expf(m[i] - mn);
                m[i] = mn;
                float r = 0.f;
#pragma unroll
                for (int j = 0; j < 4; j++) {
                    const float pv = __expf(s[i][j] - m[i]);
                    s[i][j] = pv;
                    r += pv;
                }
                rs[i] = r;
            }
#pragma unroll
            for (int off = 8; off > 0; off >>= 1)
#pragma unroll
                for (int i = 0; i < 2; i++)
                    rs[i] += __shfl_xor_sync(0xffffffffu, rs[i], off);
#pragma unroll
            for (int i = 0; i < 2; i++) {
                l[i] = l[i] * sc[i] + rs[i];
#pragma unroll
                for (int j = 0; j < 4; j++) acc[i][j] *= sc[i];
            }

            __syncthreads();
#pragma unroll
            for (int i = 0; i < 2; i++)
                *(float4*)&KP[ty*2 + i][tx*4] = make_float4(s[i][0], s[i][1], s[i][2], s[i][3]);
            __syncthreads();

#pragma unroll 8
            for (int kk = 0; kk < 64; kk += 4) {
                float4 a0 = *(float4*)&KP[ty*2 + 0][kk];
                float4 a1 = *(float4*)&KP[ty*2 + 1][kk];
                float ar[2][4] = {{a0.x,a0.y,a0.z,a0.w},{a1.x,a1.y,a1.z,a1.w}};
#pragma unroll
                for (int u = 0; u < 4; u++) {
                    float4 b = *(float4*)&Vs[kk + u][tx*4];
                    float br[4] = {b.x, b.y, b.z, b.w};
#pragma unroll
                    for (int i = 0; i < 2; i++)
#pragma unroll
                        for (int j = 0; j < 4; j++)
                            acc[i][j] = fmaf(ar[i][u], br[j], acc[i][j]);
                }
            }
        }

        const int base = (bh * 4 + kc) * 32;
#pragma unroll
        for (int i = 0; i < 2; i++) {
            const int r = ty*2 + i;
            *(float4*)&g_pacc[(base + r) * 64 + tx*4] =
                make_float4(acc[i][0], acc[i][1], acc[i][2], acc[i][3]);
            if (tx == 0) { g_pm[base + r] = m[i]; g_pl[base + r] = l[i]; }
        }
    }
}

// ---------------- merge split-K partials ----------------
__global__ __launch_bounds__(256) void attn_gq_combine() {
    const int bh = blockIdx.x;
    const int b = bh >> 4, h = bh & 15;
    for (int idx = threadIdx.x; idx < 32 * 64; idx += 256) {
        const int r = idx >> 6, d = idx & 63;
        float M = -1e30f;
#pragma unroll
        for (int kc = 0; kc < 4; kc++)
            M = fmaxf(M, g_pm[(bh*4 + kc)*32 + r]);
        float l = 0.f, o = 0.f;
#pragma unroll
        for (int kc = 0; kc < 4; kc++) {
            const int p = (bh*4 + kc)*32 + r;
            const float w = __expf(g_pm[p] - M);
            l += w * g_pl[p];
            o += w * g_pacc[p * 64 + d];
        }
        g_attn[(b * T_SZ + (r << 6)) * DM + h * DH + d] = o / l;
    }
}

// ---------------- launch ----------------
extern "C" void kernel_launch(void* const* d_in, const int* in_sizes, int n_in,
                              void* d_out, int out_size) {
    const float *x = 0;
    const float *Wqkv = 0;
    const float *Wout = 0;
    const float *bout = 0;
    for (int i = 0; i < n_in; i++) {
        switch (in_sizes[i]) {
            case B_SZ*T_SZ*DM: x    = (const float*)d_in[i]; break;
            case DM*3*DM:      Wqkv = (const float*)d_in[i]; break;
            case DM*DM:        Wout = (const float*)d_in[i]; break;
            case DM:           bout = (const float*)d_in[i]; break;
        }
    }
    float* out = (float*)d_out;

    cudaFuncSetAttribute(qkv_tc_kernel, cudaFuncAttributeMaxDynamicSharedMemorySize, GEMM_SMEM);
    cudaFuncSetAttribute(out_tc_kernel, cudaFuncAttributeMaxDynamicSharedMemorySize, GEMM_SMEM);
    cudaFuncSetAttribute(attn_fused_kernel, cudaFuncAttributeMaxDynamicSharedMemorySize, ATTN_SMEM);

    __half *xh, *wqh, *woh, *ah;
    float* attn_f;
    cudaGetSymbolAddress((void**)&xh,  g_xh);
    cudaGetSymbolAddress((void**)&wqh, g_wqh);
    cudaGetSymbolAddress((void**)&woh, g_woh);
    cudaGetSymbolAddress((void**)&ah,  g_ah);
    cudaGetSymbolAddress((void**)&attn_f, g_attn);

    rope_table_kernel<<<(T_SZ*HALF + 255) / 256, 256>>>();
    cvt_f16_kernel<<<(B_SZ*T_SZ*DM/8 + 255) / 256, 256>>>(x, xh, B_SZ*T_SZ*DM/8);
    cvt_f16_kernel<<<(DM*3*DM/8 + 255) / 256, 256>>>(Wqkv, wqh, DM*3*DM/8);
    cvt_f16_kernel<<<(DM*DM/8 + 255) / 256, 256>>>(Wout, woh, DM*DM/8);

    qkv_tc_kernel<<<dim3(3*DM/128, B_SZ*T_SZ/128), 256, GEMM_SMEM>>>();
    attn_fused_kernel<<<1024 + 256, 256, ATTN_SMEM>>>();
    attn_gq_combine<<<B_SZ*NH, 256>>>();
    cvt_f16_kernel<<<(B_SZ*T_SZ*DM/8 + 255) / 256, 256>>>(attn_f, ah, B_SZ*T_SZ*DM/8);
    out_tc_kernel<<<dim3(DM/128, B_SZ*T_SZ/128), 256, GEMM_SMEM>>>(bout, out);
}